// round 9
// baseline (speedup 1.0000x reference)
#include <cuda_runtime.h>
#include <cuda_bf16.h>
#include <cstdint>

#define GN 50000      // nodes
#define GE 800000     // edges (without self loops)
#define GIN 256       // in_dim
#define GH 8          // heads layer1
#define GHID 32       // hidden per head
#define GF1 256       // H*HID
#define GOUT 64       // classes
#define NB  ((GN + 255) / 256)

// ---------------- scratch (device globals) -------------------------------------
__device__ __nv_bfloat16 g_w1b[GIN * GF1];           // W1 bf16
__device__ __nv_bfloat16 g_w2b[GF1 * GOUT];          // W2 bf16
__device__ __nv_bfloat16 g_h1b[(size_t)GN * GF1];    // x @ W1, bf16
__device__ __nv_bfloat16 g_h2b[(size_t)GN * GOUT];   // gat1_out @ W2, bf16
__device__ float g_as1[(size_t)GN * GH];
__device__ float g_ad1[(size_t)GN * GH];
__device__ float g_as2[GN];
__device__ float g_ad2[GN];
__device__ int   g_cnt[GN];        // histogram -> cursor
__device__ int   g_rowptr[GN + 1];
__device__ int   g_srcs[GE];       // src ids bucketed by dst
__device__ int   g_bsum[NB + 1];

__device__ __forceinline__ float lrelu(float x) { return fmaxf(x, 0.2f * x); }

__device__ __forceinline__ uint32_t pack_bf16x2(float lo, float hi) {
    uint32_t r;
    asm("cvt.rn.bf16x2.f32 %0, %1, %2;" : "=r"(r) : "f"(hi), "f"(lo));
    return r;
}
__device__ __forceinline__ float2 unpack_bf16x2(uint32_t u) {
    float2 f;
    f.x = __uint_as_float(u << 16);
    f.y = __uint_as_float(u & 0xffff0000u);
    return f;
}
__device__ __forceinline__ uint32_t smem_u32(const void* p) {
    return (uint32_t)__cvta_generic_to_shared(p);
}
__device__ __forceinline__ void cp_async16(uint32_t dst, const void* src, bool pred) {
    int sz = pred ? 16 : 0;
    asm volatile("cp.async.cg.shared.global [%0], [%1], 16, %2;\n"
                 :: "r"(dst), "l"(src), "r"(sz));
}
__device__ __forceinline__ void cp_commit() {
    asm volatile("cp.async.commit_group;\n");
}
__device__ __forceinline__ void ldsm_x4(uint32_t* r, uint32_t addr) {
    asm volatile("ldmatrix.sync.aligned.m8n8.x4.shared.b16 {%0,%1,%2,%3}, [%4];\n"
                 : "=r"(r[0]), "=r"(r[1]), "=r"(r[2]), "=r"(r[3]) : "r"(addr));
}
__device__ __forceinline__ void ldsm_x4_t(uint32_t* r, uint32_t addr) {
    asm volatile("ldmatrix.sync.aligned.m8n8.x4.trans.shared.b16 {%0,%1,%2,%3}, [%4];\n"
                 : "=r"(r[0]), "=r"(r[1]), "=r"(r[2]), "=r"(r[3]) : "r"(addr));
}
__device__ __forceinline__ void mma_bf16(float* c, const uint32_t* a, uint32_t b0, uint32_t b1) {
    asm volatile(
        "mma.sync.aligned.m16n8k16.row.col.f32.bf16.bf16.f32 "
        "{%0,%1,%2,%3},{%4,%5,%6,%7},{%8,%9},{%0,%1,%2,%3};\n"
        : "+f"(c[0]), "+f"(c[1]), "+f"(c[2]), "+f"(c[3])
        : "r"(a[0]), "r"(a[1]), "r"(a[2]), "r"(a[3]), "r"(b0), "r"(b1));
}

// ---------------- CSR build (side stream) --------------------------------------
__global__ void hist_kernel(const int* __restrict__ ei, int E) {
    int i = blockIdx.x * blockDim.x + threadIdx.x;
    int n4 = E >> 2;
    if (i < n4) {
        int4 d = reinterpret_cast<const int4*>(ei + E)[i];
        atomicAdd(&g_cnt[d.x], 1);
        atomicAdd(&g_cnt[d.y], 1);
        atomicAdd(&g_cnt[d.z], 1);
        atomicAdd(&g_cnt[d.w], 1);
    } else if (i < n4 + (E & 3)) {
        atomicAdd(&g_cnt[ei[E + n4 * 4 + (i - n4)]], 1);
    }
}

__global__ void block_sum_kernel() {
    __shared__ int ws[8];
    int i = blockIdx.x * 256 + threadIdx.x;
    int v = (i < GN) ? g_cnt[i] : 0;
    int s = v;
    #pragma unroll
    for (int o = 16; o; o >>= 1) s += __shfl_xor_sync(0xffffffffu, s, o);
    if ((threadIdx.x & 31) == 0) ws[threadIdx.x >> 5] = s;
    __syncthreads();
    if (threadIdx.x < 8) {
        int t = ws[threadIdx.x];
        #pragma unroll
        for (int o = 4; o; o >>= 1) t += __shfl_xor_sync(0xffu, t, o);
        if (threadIdx.x == 0) g_bsum[blockIdx.x] = t;
    }
}

__global__ void scan_apply_kernel() {
    __shared__ int ws[8];
    __shared__ int s_off;
    int tid = threadIdx.x, lane = tid & 31, wid = tid >> 5;

    int a = 0;
    for (int j = tid; j < blockIdx.x; j += 256) a += g_bsum[j];
    #pragma unroll
    for (int o = 16; o; o >>= 1) a += __shfl_xor_sync(0xffffffffu, a, o);
    if (lane == 0) ws[wid] = a;
    __syncthreads();
    if (tid == 0) {
        int t = 0;
        #pragma unroll
        for (int k = 0; k < 8; k++) t += ws[k];
        s_off = t;
    }
    __syncthreads();

    int i = blockIdx.x * 256 + tid;
    int v = (i < GN) ? g_cnt[i] : 0;
    int s = v;
    #pragma unroll
    for (int o = 1; o < 32; o <<= 1) {
        int t = __shfl_up_sync(0xffffffffu, s, o);
        if (lane >= o) s += t;
    }
    if (lane == 31) ws[wid] = s;
    __syncthreads();
    if (wid == 0 && lane < 8) {
        int t = ws[lane];
        #pragma unroll
        for (int o = 1; o < 8; o <<= 1) {
            int u = __shfl_up_sync(0xffu, t, o);
            if (lane >= o) t += u;
        }
        ws[lane] = t;
    }
    __syncthreads();
    int incl = s + (wid ? ws[wid - 1] : 0) + s_off;
    if (i < GN) {
        g_rowptr[i + 1] = incl;
        g_cnt[i] = incl - v;   // exclusive -> scatter cursor
    }
    if (i == 0) g_rowptr[0] = 0;
}

__global__ void scatter_kernel(const int* __restrict__ ei, int E) {
    int i = blockIdx.x * blockDim.x + threadIdx.x;
    int n4 = E >> 2;
    if (i < n4) {
        int4 sv = reinterpret_cast<const int4*>(ei)[i];
        int4 dv = reinterpret_cast<const int4*>(ei + E)[i];
        g_srcs[atomicAdd(&g_cnt[dv.x], 1)] = sv.x;
        g_srcs[atomicAdd(&g_cnt[dv.y], 1)] = sv.y;
        g_srcs[atomicAdd(&g_cnt[dv.z], 1)] = sv.z;
        g_srcs[atomicAdd(&g_cnt[dv.w], 1)] = sv.w;
    } else if (i < n4 + (E & 3)) {
        int e = n4 * 4 + (i - n4);
        g_srcs[atomicAdd(&g_cnt[ei[E + e]], 1)] = ei[e];
    }
}

// ---------------- W1/W2 fp32 -> bf16 (main stream, before gemm1) ---------------
__global__ void convw_kernel(const float* __restrict__ W1, const float* __restrict__ W2) {
    int i = blockIdx.x * blockDim.x + threadIdx.x;
    int stride = gridDim.x * blockDim.x;
    const int T1 = GIN * GF1 / 8;
    for (int t = i; t < T1; t += stride) {
        float4 v0 = reinterpret_cast<const float4*>(W1)[t * 2];
        float4 v1 = reinterpret_cast<const float4*>(W1)[t * 2 + 1];
        uint4 u = make_uint4(pack_bf16x2(v0.x, v0.y), pack_bf16x2(v0.z, v0.w),
                             pack_bf16x2(v1.x, v1.y), pack_bf16x2(v1.z, v1.w));
        reinterpret_cast<uint4*>(g_w1b)[t] = u;
    }
    const int T2 = GF1 * GOUT / 8;
    for (int t = i; t < T2; t += stride) {
        float4 v0 = reinterpret_cast<const float4*>(W2)[t * 2];
        float4 v1 = reinterpret_cast<const float4*>(W2)[t * 2 + 1];
        uint4 u = make_uint4(pack_bf16x2(v0.x, v0.y), pack_bf16x2(v0.z, v0.w),
                             pack_bf16x2(v1.x, v1.y), pack_bf16x2(v1.z, v1.w));
        reinterpret_cast<uint4*>(g_w2b)[t] = u;
    }
}

// ---------------- GEMM1: A fp32 (x), B bf16 (W1), BM=64 BN=256 -----------------
__global__ void __launch_bounds__(256) gemm1_kernel(
    const float* __restrict__ A, const __nv_bfloat16* __restrict__ B,
    __nv_bfloat16* __restrict__ C,
    const float* __restrict__ a_src, const float* __restrict__ a_dst,
    float* __restrict__ g_as, float* __restrict__ g_ad) {
    constexpr int BN = 256, SBS = BN + 8;
    constexpr int A_ELEM = 64 * 40;
    constexpr int B_ELEM = 32 * SBS;
    __shared__ __align__(16) __nv_bfloat16 sA[2][A_ELEM];
    __shared__ __align__(16) __nv_bfloat16 sB[2][B_ELEM];

    const int tid = threadIdx.x, lane = tid & 31, wid = tid >> 5;
    const int warpM = wid & 1, warpN = wid >> 1;      // 2 x 4
    const int rowBase = blockIdx.x * 64;
    const int wcb = warpN * 64;

    const uint32_t sAu = smem_u32(&sA[0][0]), sBu = smem_u32(&sB[0][0]);
    const int aRow = warpM * 32 + (lane & 7) + ((lane >> 3) & 1) * 8;
    const uint32_t aAddr = sAu + (uint32_t)(aRow * 40 + ((lane >> 4) * 8)) * 2;
    const int bRow = (lane & 7) + ((lane >> 3) & 1) * 8;
    const uint32_t bAddr = sBu + (uint32_t)(bRow * SBS + wcb + (lane >> 4) * 8) * 2;

    const int ar0 = tid >> 3, ac0 = (tid & 7) * 4;
    const int ar1 = (tid + 256) >> 3, ac1 = ac0;

    auto ldA = [&](float4* r, int k0) {
        int row0 = rowBase + ar0, row1 = rowBase + ar1;
        r[0] = (row0 < GN) ? *reinterpret_cast<const float4*>(A + (size_t)row0 * GIN + k0 + ac0)
                           : make_float4(0.f, 0.f, 0.f, 0.f);
        r[1] = (row1 < GN) ? *reinterpret_cast<const float4*>(A + (size_t)row1 * GIN + k0 + ac1)
                           : make_float4(0.f, 0.f, 0.f, 0.f);
    };
    auto stA = [&](int buf, const float4* r) {
        uint2 p0 = make_uint2(pack_bf16x2(r[0].x, r[0].y), pack_bf16x2(r[0].z, r[0].w));
        uint2 p1 = make_uint2(pack_bf16x2(r[1].x, r[1].y), pack_bf16x2(r[1].z, r[1].w));
        *reinterpret_cast<uint2*>(&sA[buf][ar0 * 40 + ac0]) = p0;
        *reinterpret_cast<uint2*>(&sA[buf][ar1 * 40 + ac1]) = p1;
    };
    auto stageB = [&](int buf, int k0) {
        #pragma unroll
        for (int i2 = 0; i2 < 4; i2++) {
            int f = tid + i2 * 256;
            int krow = f >> 5, c8 = (f & 31) * 8;
            uint32_t dst = sBu + (uint32_t)(buf * B_ELEM + krow * SBS + c8) * 2;
            cp_async16(dst, B + (size_t)(k0 + krow) * BN + c8, true);
        }
    };

    float c[2][8][4];
    #pragma unroll
    for (int i = 0; i < 2; i++)
        #pragma unroll
        for (int j = 0; j < 8; j++)
            #pragma unroll
            for (int q = 0; q < 4; q++) c[i][j][q] = 0.f;

    constexpr int S = GIN / 32;
    float4 ra[2];
    ldA(ra, 0);
    stA(0, ra);
    stageB(0, 0);
    cp_commit();

    float4 rn[2];
    for (int s = 0; s < S; s++) {
        const int buf = s & 1;
        if (s + 1 < S) {
            ldA(rn, (s + 1) * 32);
            stageB(buf ^ 1, (s + 1) * 32);
            cp_commit();
            asm volatile("cp.async.wait_group 1;\n");
        } else {
            asm volatile("cp.async.wait_group 0;\n");
        }
        __syncthreads();
        const uint32_t aB = aAddr + buf * A_ELEM * 2;
        const uint32_t bB = bAddr + buf * B_ELEM * 2;
        #pragma unroll
        for (int ks = 0; ks < 2; ks++) {
            uint32_t a[2][4];
            #pragma unroll
            for (int mt = 0; mt < 2; mt++)
                ldsm_x4(a[mt], aB + (uint32_t)(mt * 16 * 40 + ks * 16) * 2);
            uint32_t b[4][4];
            #pragma unroll
            for (int np = 0; np < 4; np++)
                ldsm_x4_t(b[np], bB + (uint32_t)(ks * 16 * SBS + np * 16) * 2);
            #pragma unroll
            for (int mt = 0; mt < 2; mt++)
                #pragma unroll
                for (int nt = 0; nt < 8; nt++) {
                    int np = nt >> 1;
                    mma_bf16(c[mt][nt], a[mt], b[np][(nt & 1) * 2], b[np][(nt & 1) * 2 + 1]);
                }
        }
        if (s + 1 < S) stA(buf ^ 1, rn);
        __syncthreads();
    }

    #pragma unroll
    for (int mt = 0; mt < 2; mt++)
        #pragma unroll
        for (int half = 0; half < 2; half++) {
            int row = rowBase + warpM * 32 + mt * 16 + (lane >> 2) + half * 8;
            if (row < GN) {
                #pragma unroll
                for (int nt = 0; nt < 8; nt++) {
                    int col = wcb + nt * 8 + (lane & 3) * 2;
                    uint32_t u = pack_bf16x2(c[mt][nt][half * 2], c[mt][nt][half * 2 + 1]);
                    *reinterpret_cast<uint32_t*>(C + (size_t)row * GF1 + col) = u;
                }
            }
        }

    float asc[16], adc[16];
    #pragma unroll
    for (int nt = 0; nt < 8; nt++)
        #pragma unroll
        for (int j = 0; j < 2; j++) {
            int col = wcb + nt * 8 + (lane & 3) * 2 + j;
            asc[nt * 2 + j] = a_src[col];
            adc[nt * 2 + j] = a_dst[col];
        }
    int headBase = wcb >> 5;
    #pragma unroll
    for (int mt = 0; mt < 2; mt++)
        #pragma unroll
        for (int half = 0; half < 2; half++) {
            int row = rowBase + warpM * 32 + mt * 16 + (lane >> 2) + half * 8;
            float ss0 = 0.f, ss1 = 0.f, sd0 = 0.f, sd1 = 0.f;
            #pragma unroll
            for (int nt = 0; nt < 8; nt++)
                #pragma unroll
                for (int j = 0; j < 2; j++) {
                    float v = c[mt][nt][half * 2 + j];
                    if (nt < 4) { ss0 += v * asc[nt * 2 + j]; sd0 += v * adc[nt * 2 + j]; }
                    else        { ss1 += v * asc[nt * 2 + j]; sd1 += v * adc[nt * 2 + j]; }
                }
            #pragma unroll
            for (int o = 1; o <= 2; o <<= 1) {
                ss0 += __shfl_xor_sync(0xffffffffu, ss0, o);
                ss1 += __shfl_xor_sync(0xffffffffu, ss1, o);
                sd0 += __shfl_xor_sync(0xffffffffu, sd0, o);
                sd1 += __shfl_xor_sync(0xffffffffu, sd1, o);
            }
            if ((lane & 3) == 0 && row < GN) {
                g_as[(size_t)row * GH + headBase]     = ss0;
                g_as[(size_t)row * GH + headBase + 1] = ss1;
                g_ad[(size_t)row * GH + headBase]     = sd0;
                g_ad[(size_t)row * GH + headBase + 1] = sd1;
            }
        }
}

// ---------------- fused: agg1 (64 dsts/block) + GEMM2 + alpha2 -----------------
// Phase 1: warp-per-dst aggregation (8 dsts per warp) -> smem A tile [64][264]
// (cp.async preloads full W2 [256][72] during phase 1).
// Phase 2: GEMM2 64x64x256 from smem, h2 stored bf16, alpha2 via smem reduce.
#define FM_A_STRIDE 264
#define FM_B_STRIDE 72
#define FM_SMEM (64 * FM_A_STRIDE * 2 + 256 * FM_B_STRIDE * 2)

__global__ void __launch_bounds__(256) fused_mid_kernel(
    const float* __restrict__ b1, const __nv_bfloat16* __restrict__ W2b,
    __nv_bfloat16* __restrict__ H2,
    const float* __restrict__ a_src2, const float* __restrict__ a_dst2,
    float* __restrict__ gas2, float* __restrict__ gad2) {
    extern __shared__ __align__(16) char dyn[];
    __nv_bfloat16* sA = reinterpret_cast<__nv_bfloat16*>(dyn);          // [64][264]
    __nv_bfloat16* sB = sA + 64 * FM_A_STRIDE;                          // [256][72]
    const int tid = threadIdx.x, lane = tid & 31, wid = tid >> 5;
    const int rowBase = blockIdx.x * 64;
    const uint32_t sAu = smem_u32(sA), sBu = smem_u32(sB);

    // preload full B = W2 (256 x 64 bf16 = 32KB), overlapped with phase 1
    #pragma unroll
    for (int i = 0; i < 8; i++) {
        int f = tid + i * 256;               // 2048 chunks of 16B
        int krow = f >> 3, c8 = (f & 7) * 8;
        cp_async16(sBu + (uint32_t)(krow * FM_B_STRIDE + c8) * 2, W2b + krow * GOUT + c8, true);
    }
    cp_commit();

    // ---- phase 1: aggregation, 8 dsts per warp
    const int head = lane >> 2;
    float4 bb0 = *reinterpret_cast<const float4*>(b1 + lane * 8);
    float4 bb1 = *reinterpret_cast<const float4*>(b1 + lane * 8 + 4);
    float bv[8] = {bb0.x, bb0.y, bb0.z, bb0.w, bb1.x, bb1.y, bb1.z, bb1.w};

    for (int i = 0; i < 8; i++) {
        int rowLocal = wid * 8 + i;
        int dst = rowBase + rowLocal;
        if (dst >= GN) {
            *reinterpret_cast<uint4*>(&sA[rowLocal * FM_A_STRIDE + lane * 8]) =
                make_uint4(0, 0, 0, 0);
            continue;
        }
        const float ad = g_ad1[(size_t)dst * GH + head];
        const int rs = g_rowptr[dst];
        const int re = g_rowptr[dst + 1];

        // depth-2 prefetch
        uint4 u0 = make_uint4(0, 0, 0, 0), u1 = make_uint4(0, 0, 0, 0);
        float a0v = 0.f, a1v = 0.f;
        if (rs < re) {
            int s0 = g_srcs[rs];
            u0 = *reinterpret_cast<const uint4*>(g_h1b + (size_t)s0 * GF1 + lane * 8);
            a0v = g_as1[(size_t)s0 * GH + head];
        }
        if (rs + 1 < re) {
            int s1 = g_srcs[rs + 1];
            u1 = *reinterpret_cast<const uint4*>(g_h1b + (size_t)s1 * GF1 + lane * 8);
            a1v = g_as1[(size_t)s1 * GH + head];
        }

        float acc[8], den;
        {   // self loop
            float w = __expf(lrelu(g_as1[(size_t)dst * GH + head] + ad));
            den = w;
            uint4 us = *reinterpret_cast<const uint4*>(g_h1b + (size_t)dst * GF1 + lane * 8);
            float2 f0 = unpack_bf16x2(us.x), f1 = unpack_bf16x2(us.y);
            float2 f2 = unpack_bf16x2(us.z), f3 = unpack_bf16x2(us.w);
            acc[0] = w * f0.x; acc[1] = w * f0.y; acc[2] = w * f1.x; acc[3] = w * f1.y;
            acc[4] = w * f2.x; acc[5] = w * f2.y; acc[6] = w * f3.x; acc[7] = w * f3.y;
        }
        for (int e = rs; e < re; e++) {
            uint4 uc = u0;
            float ac = a0v;
            u0 = u1; a0v = a1v;
            if (e + 2 < re) {
                int s2 = g_srcs[e + 2];
                u1 = *reinterpret_cast<const uint4*>(g_h1b + (size_t)s2 * GF1 + lane * 8);
                a1v = g_as1[(size_t)s2 * GH + head];
            }
            float w = __expf(lrelu(ac + ad));
            den += w;
            float2 f0 = unpack_bf16x2(uc.x), f1 = unpack_bf16x2(uc.y);
            float2 f2 = unpack_bf16x2(uc.z), f3 = unpack_bf16x2(uc.w);
            acc[0] += w * f0.x; acc[1] += w * f0.y; acc[2] += w * f1.x; acc[3] += w * f1.y;
            acc[4] += w * f2.x; acc[5] += w * f2.y; acc[6] += w * f3.x; acc[7] += w * f3.y;
        }
        float inv = 1.f / den;
        uint4 st;
        uint32_t* stp = reinterpret_cast<uint32_t*>(&st);
        #pragma unroll
        for (int p = 0; p < 4; p++) {
            float v0 = fmaxf(acc[2 * p] * inv + bv[2 * p], 0.f);
            float v1 = fmaxf(acc[2 * p + 1] * inv + bv[2 * p + 1], 0.f);
            stp[p] = pack_bf16x2(v0, v1);
        }
        *reinterpret_cast<uint4*>(&sA[rowLocal * FM_A_STRIDE + lane * 8]) = st;
    }
    asm volatile("cp.async.wait_group 0;\n");
    __syncthreads();

    // ---- phase 2: GEMM2 (64x64x256) from smem
    const int warpM = wid & 1, warpN = wid >> 1;     // 2 x 4
    const int aRow = warpM * 32 + (lane & 7) + ((lane >> 3) & 1) * 8;
    const uint32_t aAddr = sAu + (uint32_t)(aRow * FM_A_STRIDE + (lane >> 4) * 8) * 2;
    const int bRow = (lane & 7) + ((lane >> 3) & 1) * 8;
    const uint32_t bAddr = sBu + (uint32_t)(bRow * FM_B_STRIDE + warpN * 16 + (lane >> 4) * 8) * 2;

    float c[2][2][4];
    #pragma unroll
    for (int i = 0; i < 2; i++)
        #pragma unroll
        for (int j = 0; j < 2; j++)
            #pragma unroll
            for (int q = 0; q < 4; q++) c[i][j][q] = 0.f;

    #pragma unroll
    for (int s = 0; s < 8; s++) {
        #pragma unroll
        for (int ks = 0; ks < 2; ks++) {
            uint32_t a[2][4];
            #pragma unroll
            for (int mt = 0; mt < 2; mt++)
                ldsm_x4(a[mt], aAddr + (uint32_t)(mt * 16 * FM_A_STRIDE + s * 32 + ks * 16) * 2);
            uint32_t b[4];
            ldsm_x4_t(b, bAddr + (uint32_t)((s * 32 + ks * 16) * FM_B_STRIDE) * 2);
            #pragma unroll
            for (int mt = 0; mt < 2; mt++) {
                mma_bf16(c[mt][0], a[mt], b[0], b[1]);
                mma_bf16(c[mt][1], a[mt], b[2], b[3]);
            }
        }
    }

    // store h2 (bf16)
    #pragma unroll
    for (int mt = 0; mt < 2; mt++)
        #pragma unroll
        for (int half = 0; half < 2; half++) {
            int row = rowBase + warpM * 32 + mt * 16 + (lane >> 2) + half * 8;
            if (row < GN) {
                #pragma unroll
                for (int nt = 0; nt < 2; nt++) {
                    int col = warpN * 16 + nt * 8 + (lane & 3) * 2;
                    uint32_t u = pack_bf16x2(c[mt][nt][half * 2], c[mt][nt][half * 2 + 1]);
                    *reinterpret_cast<uint32_t*>(H2 + (size_t)row * GOUT + col) = u;
                }
            }
        }

    // fused alpha2: per-warp 16-col partial dot, cross-warp (4 warpN) smem reduce
    float* sP = reinterpret_cast<float*>(dyn);    // [64][8], reuses sA region
    __syncthreads();
    float asc[4], adc[4];
    #pragma unroll
    for (int nt = 0; nt < 2; nt++)
        #pragma unroll
        for (int j = 0; j < 2; j++) {
            int col = warpN * 16 + nt * 8 + (lane & 3) * 2 + j;
            asc[nt * 2 + j] = a_src2[col];
            adc[nt * 2 + j] = a_dst2[col];
        }
    #pragma unroll
    for (int mt = 0; mt < 2; mt++)
        #pragma unroll
        for (int half = 0; half < 2; half++) {
            float ss = 0.f, sd = 0.f;
            #pragma unroll
            for (int nt = 0; nt < 2; nt++)
                #pragma unroll
                for (int j = 0; j < 2; j++) {
                    float v = c[mt][nt][half * 2 + j];
                    ss += v * asc[nt * 2 + j];
                    sd += v * adc[nt * 2 + j];
                }
            #pragma unroll
            for (int o = 1; o <= 2; o <<= 1) {
                ss += __shfl_xor_sync(0xffffffffu, ss, o);
                sd += __shfl_xor_sync(0xffffffffu, sd, o);
            }
            if ((lane & 3) == 0) {
                int rl = warpM * 32 + mt * 16 + (lane >> 2) + half * 8;
                sP[rl * 8 + warpN * 2 + 0] = ss;
                sP[rl * 8 + warpN * 2 + 1] = sd;
            }
        }
    __syncthreads();
    if (tid < 64) {
        int row = rowBase + tid;
        if (row < GN) {
            gas2[row] = sP[tid * 8 + 0] + sP[tid * 8 + 2] + sP[tid * 8 + 4] + sP[tid * 8 + 6];
            gad2[row] = sP[tid * 8 + 1] + sP[tid * 8 + 3] + sP[tid * 8 + 5] + sP[tid * 8 + 7];
        }
    }
}

// ---------------- layer-2 aggregation + bias + log_softmax ---------------------
__global__ void __launch_bounds__(256) agg2_kernel(const float* __restrict__ b2,
                                                   float* __restrict__ out) {
    int dst = (blockIdx.x * blockDim.x + threadIdx.x) >> 5;
    int lane = threadIdx.x & 31;
    if (dst >= GN) return;

    const float ad = g_ad2[dst];
    const int rs = g_rowptr[dst];
    const int re = g_rowptr[dst + 1];

    // depth-2 prefetch
    uint32_t u0 = 0, u1 = 0;
    float a0v = 0.f, a1v = 0.f;
    if (rs < re) {
        int s0 = g_srcs[rs];
        u0 = *reinterpret_cast<const uint32_t*>(g_h2b + (size_t)s0 * GOUT + 2 * lane);
        a0v = g_as2[s0];
    }
    if (rs + 1 < re) {
        int s1 = g_srcs[rs + 1];
        u1 = *reinterpret_cast<const uint32_t*>(g_h2b + (size_t)s1 * GOUT + 2 * lane);
        a1v = g_as2[s1];
    }

    float den, a0, a1;
    {
        float w = __expf(lrelu(g_as2[dst] + ad));
        den = w;
        uint32_t us = *reinterpret_cast<const uint32_t*>(g_h2b + (size_t)dst * GOUT + 2 * lane);
        float2 f = unpack_bf16x2(us);
        a0 = w * f.x;
        a1 = w * f.y;
    }
    for (int e = rs; e < re; e++) {
        uint32_t uc = u0;
        float ac = a0v;
        u0 = u1; a0v = a1v;
        if (e + 2 < re) {
            int s2 = g_srcs[e + 2];
            u1 = *reinterpret_cast<const uint32_t*>(g_h2b + (size_t)s2 * GOUT + 2 * lane);
            a1v = g_as2[s2];
        }
        float w = __expf(lrelu(ac + ad));
        den += w;
        float2 f = unpack_bf16x2(uc);
        a0 += w * f.x;
        a1 += w * f.y;
    }
    float2 bb = *reinterpret_cast<const float2*>(b2 + 2 * lane);
    float inv = 1.f / den;
    float v0 = a0 * inv + bb.x;
    float v1 = a1 * inv + bb.y;

    float m = fmaxf(v0, v1);
    #pragma unroll
    for (int o = 16; o; o >>= 1) m = fmaxf(m, __shfl_xor_sync(0xffffffffu, m, o));
    float s = __expf(v0 - m) + __expf(v1 - m);
    #pragma unroll
    for (int o = 16; o; o >>= 1) s += __shfl_xor_sync(0xffffffffu, s, o);
    float ls = __logf(s) + m;

    float2 st = make_float2(v0 - ls, v1 - ls);
    *reinterpret_cast<float2*>(out + (size_t)dst * GOUT + 2 * lane) = st;
}

// ---------------- launch --------------------------------------------------------
extern "C" void kernel_launch(void* const* d_in, const int* in_sizes, int n_in,
                              void* d_out, int out_size) {
    const float* x      = (const float*)d_in[0];
    const int*   ei     = (const int*)d_in[1];
    const float* W1     = (const float*)d_in[2];
    const float* a_src1 = (const float*)d_in[3];
    const float* a_dst1 = (const float*)d_in[4];
    const float* b1     = (const float*)d_in[5];
    const float* W2     = (const float*)d_in[6];
    const float* a_src2 = (const float*)d_in[7];
    const float* a_dst2 = (const float*)d_in[8];
    const float* b2     = (const float*)d_in[9];
    float* out = (float*)d_out;
    const int E = in_sizes[1] / 2;

    __nv_bfloat16 *w1p, *w2p, *h1p, *h2p;
    float *as1p, *ad1p, *as2p, *ad2p;
    void* cntp;
    cudaGetSymbolAddress((void**)&w1p, g_w1b);
    cudaGetSymbolAddress((void**)&w2p, g_w2b);
    cudaGetSymbolAddress((void**)&h1p, g_h1b);
    cudaGetSymbolAddress((void**)&h2p, g_h2b);
    cudaGetSymbolAddress((void**)&as1p, g_as1);
    cudaGetSymbolAddress((void**)&ad1p, g_ad1);
    cudaGetSymbolAddress((void**)&as2p, g_as2);
    cudaGetSymbolAddress((void**)&ad2p, g_ad2);
    cudaGetSymbolAddress(&cntp, g_cnt);

    // host-side resources, created once
    static cudaStream_t s_side = nullptr;
    static cudaEvent_t s_fork = nullptr, s_join = nullptr;
    if (s_side == nullptr) {
        cudaStreamCreateWithFlags(&s_side, cudaStreamNonBlocking);
        cudaEventCreateWithFlags(&s_fork, cudaEventDisableTiming);
        cudaEventCreateWithFlags(&s_join, cudaEventDisableTiming);
        cudaFuncSetAttribute(fused_mid_kernel,
                             cudaFuncAttributeMaxDynamicSharedMemorySize, FM_SMEM);
    }

    // fork: CSR chain on side stream, GEMM1 chain on main stream
    cudaEventRecord(s_fork, 0);
    cudaStreamWaitEvent(s_side, s_fork, 0);

    // --- side: CSR build
    cudaMemsetAsync(cntp, 0, GN * sizeof(int), s_side);
    hist_kernel<<<(E / 4 + 4 + 255) / 256, 256, 0, s_side>>>(ei, E);
    block_sum_kernel<<<NB, 256, 0, s_side>>>();
    scan_apply_kernel<<<NB, 256, 0, s_side>>>();
    scatter_kernel<<<(E / 4 + 4 + 255) / 256, 256, 0, s_side>>>(ei, E);
    cudaEventRecord(s_join, s_side);

    // --- main: W conversion + GEMM1 (+ fused alpha1)
    convw_kernel<<<132, 256>>>(W1, W2);
    gemm1_kernel<<<(GN + 63) / 64, 256>>>(x, w1p, h1p, a_src1, a_dst1, as1p, ad1p);

    // join
    cudaStreamWaitEvent(0, s_join, 0);

    // fused agg1 + GEMM2 + alpha2, then final aggregation
    fused_mid_kernel<<<(GN + 63) / 64, 256, FM_SMEM>>>(
        b1, w2p, h2p, a_src2, a_dst2, as2p, ad2p);
    agg2_kernel<<<(GN + 7) / 8, 256>>>(b2, out);
}

// round 10
// speedup vs baseline: 1.2137x; 1.2137x over previous
#include <cuda_runtime.h>
#include <cuda_bf16.h>
#include <cstdint>

#define GN 50000      // nodes
#define GE 800000     // edges (without self loops)
#define GIN 256       // in_dim
#define GH 8          // heads layer1
#define GHID 32       // hidden per head
#define GF1 256       // H*HID
#define GOUT 64       // classes
#define NB  ((GN + 255) / 256)

// ---------------- scratch (device globals) -------------------------------------
__device__ __nv_bfloat16 g_w1b[GIN * GF1];           // W1 bf16
__device__ __nv_bfloat16 g_w2b[GF1 * GOUT];          // W2 bf16
__device__ __nv_bfloat16 g_h1b[(size_t)GN * GF1];    // x @ W1, bf16
__device__ __nv_bfloat16 g_out1b[(size_t)GN * GF1];  // relu(gat1), bf16
__device__ __nv_bfloat16 g_h2b[(size_t)GN * GOUT];   // gat1_out @ W2, bf16
__device__ float g_as1[(size_t)GN * GH];
__device__ float g_ad1[(size_t)GN * GH];
__device__ float g_as2[GN];
__device__ float g_ad2[GN];
__device__ int   g_cnt[GN];        // histogram -> cursor
__device__ int   g_rowptr[GN + 1];
__device__ int   g_srcs[GE];       // src ids bucketed by dst
__device__ int   g_bsum[NB + 1];

__device__ __forceinline__ float lrelu(float x) { return fmaxf(x, 0.2f * x); }

__device__ __forceinline__ uint32_t pack_bf16x2(float lo, float hi) {
    uint32_t r;
    asm("cvt.rn.bf16x2.f32 %0, %1, %2;" : "=r"(r) : "f"(hi), "f"(lo));
    return r;
}
__device__ __forceinline__ float2 unpack_bf16x2(uint32_t u) {
    float2 f;
    f.x = __uint_as_float(u << 16);
    f.y = __uint_as_float(u & 0xffff0000u);
    return f;
}
__device__ __forceinline__ uint32_t smem_u32(const void* p) {
    return (uint32_t)__cvta_generic_to_shared(p);
}
__device__ __forceinline__ void cp_async16(uint32_t dst, const void* src, bool pred) {
    int sz = pred ? 16 : 0;
    asm volatile("cp.async.cg.shared.global [%0], [%1], 16, %2;\n"
                 :: "r"(dst), "l"(src), "r"(sz));
}
__device__ __forceinline__ void cp_commit() {
    asm volatile("cp.async.commit_group;\n");
}
__device__ __forceinline__ void ldsm_x4(uint32_t* r, uint32_t addr) {
    asm volatile("ldmatrix.sync.aligned.m8n8.x4.shared.b16 {%0,%1,%2,%3}, [%4];\n"
                 : "=r"(r[0]), "=r"(r[1]), "=r"(r[2]), "=r"(r[3]) : "r"(addr));
}
__device__ __forceinline__ void ldsm_x4_t(uint32_t* r, uint32_t addr) {
    asm volatile("ldmatrix.sync.aligned.m8n8.x4.trans.shared.b16 {%0,%1,%2,%3}, [%4];\n"
                 : "=r"(r[0]), "=r"(r[1]), "=r"(r[2]), "=r"(r[3]) : "r"(addr));
}
__device__ __forceinline__ void mma_bf16(float* c, const uint32_t* a, uint32_t b0, uint32_t b1) {
    asm volatile(
        "mma.sync.aligned.m16n8k16.row.col.f32.bf16.bf16.f32 "
        "{%0,%1,%2,%3},{%4,%5,%6,%7},{%8,%9},{%0,%1,%2,%3};\n"
        : "+f"(c[0]), "+f"(c[1]), "+f"(c[2]), "+f"(c[3])
        : "r"(a[0]), "r"(a[1]), "r"(a[2]), "r"(a[3]), "r"(b0), "r"(b1));
}

// ---------------- CSR build (side stream) --------------------------------------
__global__ void hist_kernel(const int* __restrict__ ei, int E) {
    int i = blockIdx.x * blockDim.x + threadIdx.x;
    int n4 = E >> 2;
    if (i < n4) {
        int4 d = reinterpret_cast<const int4*>(ei + E)[i];
        atomicAdd(&g_cnt[d.x], 1);
        atomicAdd(&g_cnt[d.y], 1);
        atomicAdd(&g_cnt[d.z], 1);
        atomicAdd(&g_cnt[d.w], 1);
    } else if (i < n4 + (E & 3)) {
        atomicAdd(&g_cnt[ei[E + n4 * 4 + (i - n4)]], 1);
    }
}

__global__ void block_sum_kernel() {
    __shared__ int ws[8];
    int i = blockIdx.x * 256 + threadIdx.x;
    int v = (i < GN) ? g_cnt[i] : 0;
    int s = v;
    #pragma unroll
    for (int o = 16; o; o >>= 1) s += __shfl_xor_sync(0xffffffffu, s, o);
    if ((threadIdx.x & 31) == 0) ws[threadIdx.x >> 5] = s;
    __syncthreads();
    if (threadIdx.x < 8) {
        int t = ws[threadIdx.x];
        #pragma unroll
        for (int o = 4; o; o >>= 1) t += __shfl_xor_sync(0xffu, t, o);
        if (threadIdx.x == 0) g_bsum[blockIdx.x] = t;
    }
}

__global__ void scan_apply_kernel() {
    __shared__ int ws[8];
    __shared__ int s_off;
    int tid = threadIdx.x, lane = tid & 31, wid = tid >> 5;

    int a = 0;
    for (int j = tid; j < blockIdx.x; j += 256) a += g_bsum[j];
    #pragma unroll
    for (int o = 16; o; o >>= 1) a += __shfl_xor_sync(0xffffffffu, a, o);
    if (lane == 0) ws[wid] = a;
    __syncthreads();
    if (tid == 0) {
        int t = 0;
        #pragma unroll
        for (int k = 0; k < 8; k++) t += ws[k];
        s_off = t;
    }
    __syncthreads();

    int i = blockIdx.x * 256 + tid;
    int v = (i < GN) ? g_cnt[i] : 0;
    int s = v;
    #pragma unroll
    for (int o = 1; o < 32; o <<= 1) {
        int t = __shfl_up_sync(0xffffffffu, s, o);
        if (lane >= o) s += t;
    }
    if (lane == 31) ws[wid] = s;
    __syncthreads();
    if (wid == 0 && lane < 8) {
        int t = ws[lane];
        #pragma unroll
        for (int o = 1; o < 8; o <<= 1) {
            int u = __shfl_up_sync(0xffu, t, o);
            if (lane >= o) t += u;
        }
        ws[lane] = t;
    }
    __syncthreads();
    int incl = s + (wid ? ws[wid - 1] : 0) + s_off;
    if (i < GN) {
        g_rowptr[i + 1] = incl;
        g_cnt[i] = incl - v;   // exclusive -> scatter cursor
    }
    if (i == 0) g_rowptr[0] = 0;
}

__global__ void scatter_kernel(const int* __restrict__ ei, int E) {
    int i = blockIdx.x * blockDim.x + threadIdx.x;
    int n4 = E >> 2;
    if (i < n4) {
        int4 sv = reinterpret_cast<const int4*>(ei)[i];
        int4 dv = reinterpret_cast<const int4*>(ei + E)[i];
        g_srcs[atomicAdd(&g_cnt[dv.x], 1)] = sv.x;
        g_srcs[atomicAdd(&g_cnt[dv.y], 1)] = sv.y;
        g_srcs[atomicAdd(&g_cnt[dv.z], 1)] = sv.z;
        g_srcs[atomicAdd(&g_cnt[dv.w], 1)] = sv.w;
    } else if (i < n4 + (E & 3)) {
        int e = n4 * 4 + (i - n4);
        g_srcs[atomicAdd(&g_cnt[ei[E + e]], 1)] = ei[e];
    }
}

// ---------------- W1/W2 fp32 -> bf16 (main stream, before gemm1) ---------------
__global__ void convw_kernel(const float* __restrict__ W1, const float* __restrict__ W2) {
    int i = blockIdx.x * blockDim.x + threadIdx.x;
    int stride = gridDim.x * blockDim.x;
    const int T1 = GIN * GF1 / 8;
    for (int t = i; t < T1; t += stride) {
        float4 v0 = reinterpret_cast<const float4*>(W1)[t * 2];
        float4 v1 = reinterpret_cast<const float4*>(W1)[t * 2 + 1];
        uint4 u = make_uint4(pack_bf16x2(v0.x, v0.y), pack_bf16x2(v0.z, v0.w),
                             pack_bf16x2(v1.x, v1.y), pack_bf16x2(v1.z, v1.w));
        reinterpret_cast<uint4*>(g_w1b)[t] = u;
    }
    const int T2 = GF1 * GOUT / 8;
    for (int t = i; t < T2; t += stride) {
        float4 v0 = reinterpret_cast<const float4*>(W2)[t * 2];
        float4 v1 = reinterpret_cast<const float4*>(W2)[t * 2 + 1];
        uint4 u = make_uint4(pack_bf16x2(v0.x, v0.y), pack_bf16x2(v0.z, v0.w),
                             pack_bf16x2(v1.x, v1.y), pack_bf16x2(v1.z, v1.w));
        reinterpret_cast<uint4*>(g_w2b)[t] = u;
    }
}

// ---------------- GEMM1: A fp32 (x), B bf16 (W1), BM=64 BN=256 -----------------
__global__ void __launch_bounds__(256) gemm1_kernel(
    const float* __restrict__ A, const __nv_bfloat16* __restrict__ B,
    __nv_bfloat16* __restrict__ C,
    const float* __restrict__ a_src, const float* __restrict__ a_dst,
    float* __restrict__ g_as, float* __restrict__ g_ad) {
    constexpr int BN = 256, SBS = BN + 8;
    constexpr int A_ELEM = 64 * 40;
    constexpr int B_ELEM = 32 * SBS;
    __shared__ __align__(16) __nv_bfloat16 sA[2][A_ELEM];
    __shared__ __align__(16) __nv_bfloat16 sB[2][B_ELEM];

    const int tid = threadIdx.x, lane = tid & 31, wid = tid >> 5;
    const int warpM = wid & 1, warpN = wid >> 1;      // 2 x 4
    const int rowBase = blockIdx.x * 64;
    const int wcb = warpN * 64;

    const uint32_t sAu = smem_u32(&sA[0][0]), sBu = smem_u32(&sB[0][0]);
    const int aRow = warpM * 32 + (lane & 7) + ((lane >> 3) & 1) * 8;
    const uint32_t aAddr = sAu + (uint32_t)(aRow * 40 + ((lane >> 4) * 8)) * 2;
    const int bRow = (lane & 7) + ((lane >> 3) & 1) * 8;
    const uint32_t bAddr = sBu + (uint32_t)(bRow * SBS + wcb + (lane >> 4) * 8) * 2;

    const int ar0 = tid >> 3, ac0 = (tid & 7) * 4;
    const int ar1 = (tid + 256) >> 3, ac1 = ac0;

    auto ldA = [&](float4* r, int k0) {
        int row0 = rowBase + ar0, row1 = rowBase + ar1;
        r[0] = (row0 < GN) ? *reinterpret_cast<const float4*>(A + (size_t)row0 * GIN + k0 + ac0)
                           : make_float4(0.f, 0.f, 0.f, 0.f);
        r[1] = (row1 < GN) ? *reinterpret_cast<const float4*>(A + (size_t)row1 * GIN + k0 + ac1)
                           : make_float4(0.f, 0.f, 0.f, 0.f);
    };
    auto stA = [&](int buf, const float4* r) {
        uint2 p0 = make_uint2(pack_bf16x2(r[0].x, r[0].y), pack_bf16x2(r[0].z, r[0].w));
        uint2 p1 = make_uint2(pack_bf16x2(r[1].x, r[1].y), pack_bf16x2(r[1].z, r[1].w));
        *reinterpret_cast<uint2*>(&sA[buf][ar0 * 40 + ac0]) = p0;
        *reinterpret_cast<uint2*>(&sA[buf][ar1 * 40 + ac1]) = p1;
    };
    auto stageB = [&](int buf, int k0) {
        #pragma unroll
        for (int i2 = 0; i2 < 4; i2++) {
            int f = tid + i2 * 256;
            int krow = f >> 5, c8 = (f & 31) * 8;
            uint32_t dst = sBu + (uint32_t)(buf * B_ELEM + krow * SBS + c8) * 2;
            cp_async16(dst, B + (size_t)(k0 + krow) * BN + c8, true);
        }
    };

    float c[2][8][4];
    #pragma unroll
    for (int i = 0; i < 2; i++)
        #pragma unroll
        for (int j = 0; j < 8; j++)
            #pragma unroll
            for (int q = 0; q < 4; q++) c[i][j][q] = 0.f;

    constexpr int S = GIN / 32;
    float4 ra[2];
    ldA(ra, 0);
    stA(0, ra);
    stageB(0, 0);
    cp_commit();

    float4 rn[2];
    for (int s = 0; s < S; s++) {
        const int buf = s & 1;
        if (s + 1 < S) {
            ldA(rn, (s + 1) * 32);
            stageB(buf ^ 1, (s + 1) * 32);
            cp_commit();
            asm volatile("cp.async.wait_group 1;\n");
        } else {
            asm volatile("cp.async.wait_group 0;\n");
        }
        __syncthreads();
        const uint32_t aB = aAddr + buf * A_ELEM * 2;
        const uint32_t bB = bAddr + buf * B_ELEM * 2;
        #pragma unroll
        for (int ks = 0; ks < 2; ks++) {
            uint32_t a[2][4];
            #pragma unroll
            for (int mt = 0; mt < 2; mt++)
                ldsm_x4(a[mt], aB + (uint32_t)(mt * 16 * 40 + ks * 16) * 2);
            uint32_t b[4][4];
            #pragma unroll
            for (int np = 0; np < 4; np++)
                ldsm_x4_t(b[np], bB + (uint32_t)(ks * 16 * SBS + np * 16) * 2);
            #pragma unroll
            for (int mt = 0; mt < 2; mt++)
                #pragma unroll
                for (int nt = 0; nt < 8; nt++) {
                    int np = nt >> 1;
                    mma_bf16(c[mt][nt], a[mt], b[np][(nt & 1) * 2], b[np][(nt & 1) * 2 + 1]);
                }
        }
        if (s + 1 < S) stA(buf ^ 1, rn);
        __syncthreads();
    }

    #pragma unroll
    for (int mt = 0; mt < 2; mt++)
        #pragma unroll
        for (int half = 0; half < 2; half++) {
            int row = rowBase + warpM * 32 + mt * 16 + (lane >> 2) + half * 8;
            if (row < GN) {
                #pragma unroll
                for (int nt = 0; nt < 8; nt++) {
                    int col = wcb + nt * 8 + (lane & 3) * 2;
                    uint32_t u = pack_bf16x2(c[mt][nt][half * 2], c[mt][nt][half * 2 + 1]);
                    *reinterpret_cast<uint32_t*>(C + (size_t)row * GF1 + col) = u;
                }
            }
        }

    float asc[16], adc[16];
    #pragma unroll
    for (int nt = 0; nt < 8; nt++)
        #pragma unroll
        for (int j = 0; j < 2; j++) {
            int col = wcb + nt * 8 + (lane & 3) * 2 + j;
            asc[nt * 2 + j] = a_src[col];
            adc[nt * 2 + j] = a_dst[col];
        }
    int headBase = wcb >> 5;
    #pragma unroll
    for (int mt = 0; mt < 2; mt++)
        #pragma unroll
        for (int half = 0; half < 2; half++) {
            int row = rowBase + warpM * 32 + mt * 16 + (lane >> 2) + half * 8;
            float ss0 = 0.f, ss1 = 0.f, sd0 = 0.f, sd1 = 0.f;
            #pragma unroll
            for (int nt = 0; nt < 8; nt++)
                #pragma unroll
                for (int j = 0; j < 2; j++) {
                    float v = c[mt][nt][half * 2 + j];
                    if (nt < 4) { ss0 += v * asc[nt * 2 + j]; sd0 += v * adc[nt * 2 + j]; }
                    else        { ss1 += v * asc[nt * 2 + j]; sd1 += v * adc[nt * 2 + j]; }
                }
            #pragma unroll
            for (int o = 1; o <= 2; o <<= 1) {
                ss0 += __shfl_xor_sync(0xffffffffu, ss0, o);
                ss1 += __shfl_xor_sync(0xffffffffu, ss1, o);
                sd0 += __shfl_xor_sync(0xffffffffu, sd0, o);
                sd1 += __shfl_xor_sync(0xffffffffu, sd1, o);
            }
            if ((lane & 3) == 0 && row < GN) {
                g_as[(size_t)row * GH + headBase]     = ss0;
                g_as[(size_t)row * GH + headBase + 1] = ss1;
                g_ad[(size_t)row * GH + headBase]     = sd0;
                g_ad[(size_t)row * GH + headBase + 1] = sd1;
            }
        }
}

// ---------------- GEMM2: bf16 A (out1), BN=64, fused alpha2 --------------------
__global__ void __launch_bounds__(256) gemm2_kernel(
    const __nv_bfloat16* __restrict__ A, const __nv_bfloat16* __restrict__ B,
    __nv_bfloat16* __restrict__ C, int M, int K, int Nc,
    const float* __restrict__ a_src, const float* __restrict__ a_dst,
    float* __restrict__ g_as, float* __restrict__ g_ad) {
    constexpr int BN = 64, NT = 4, NP = 2, SBS = BN + 8;
    constexpr int A_ELEM = 128 * 40;
    constexpr int B_ELEM = 32 * SBS;
    __shared__ __align__(16) __nv_bfloat16 sA[2][A_ELEM];
    __shared__ __align__(16) __nv_bfloat16 sB[2][B_ELEM];

    const int tid = threadIdx.x, lane = tid & 31, wid = tid >> 5;
    const int warpM = wid & 3, warpN = wid >> 2;
    const int rowBase = blockIdx.y * 128;
    const int wcb = warpN * (BN / 2);

    const uint32_t sAu = smem_u32(&sA[0][0]), sBu = smem_u32(&sB[0][0]);
    const int aRow = warpM * 32 + (lane & 7) + ((lane >> 3) & 1) * 8;
    const uint32_t aAddr = sAu + (uint32_t)(aRow * 40 + ((lane >> 4) * 8)) * 2;
    const int bRow = (lane & 7) + ((lane >> 3) & 1) * 8;
    const uint32_t bAddr = sBu + (uint32_t)(bRow * SBS + wcb + (lane >> 4) * 8) * 2;

    auto stageA = [&](int buf, int k0) {
        #pragma unroll
        for (int i2 = 0; i2 < 2; i2++) {
            int f = tid + i2 * 256;
            int r = f >> 2, c8 = (f & 3) * 8;
            int row = rowBase + r;
            uint32_t dst = sAu + (uint32_t)(buf * A_ELEM + r * 40 + c8) * 2;
            cp_async16(dst, A + (size_t)row * K + k0 + c8, row < M);
        }
    };
    auto stageB = [&](int buf, int k0) {
        int krow = tid >> 3, c8 = (tid & 7) * 8;
        uint32_t dst = sBu + (uint32_t)(buf * B_ELEM + krow * SBS + c8) * 2;
        cp_async16(dst, B + (size_t)(k0 + krow) * Nc + c8, true);
    };

    float c[2][NT][4];
    #pragma unroll
    for (int i = 0; i < 2; i++)
        #pragma unroll
        for (int j = 0; j < NT; j++)
            #pragma unroll
            for (int q = 0; q < 4; q++) c[i][j][q] = 0.f;

    const int S = K / 32;
    stageA(0, 0);
    stageB(0, 0);
    cp_commit();

    for (int s = 0; s < S; s++) {
        const int buf = s & 1;
        if (s + 1 < S) {
            stageA(buf ^ 1, (s + 1) * 32);
            stageB(buf ^ 1, (s + 1) * 32);
            cp_commit();
            asm volatile("cp.async.wait_group 1;\n");
        } else {
            asm volatile("cp.async.wait_group 0;\n");
        }
        __syncthreads();
        const uint32_t aB = aAddr + buf * A_ELEM * 2;
        const uint32_t bB = bAddr + buf * B_ELEM * 2;
        #pragma unroll
        for (int ks = 0; ks < 2; ks++) {
            uint32_t a[2][4];
            #pragma unroll
            for (int mt = 0; mt < 2; mt++)
                ldsm_x4(a[mt], aB + (uint32_t)(mt * 16 * 40 + ks * 16) * 2);
            uint32_t b[NP][4];
            #pragma unroll
            for (int np = 0; np < NP; np++)
                ldsm_x4_t(b[np], bB + (uint32_t)(ks * 16 * SBS + np * 16) * 2);
            #pragma unroll
            for (int mt = 0; mt < 2; mt++)
                #pragma unroll
                for (int nt = 0; nt < NT; nt++) {
                    int np = nt >> 1;
                    mma_bf16(c[mt][nt], a[mt], b[np][(nt & 1) * 2], b[np][(nt & 1) * 2 + 1]);
                }
        }
        __syncthreads();
    }

    #pragma unroll
    for (int mt = 0; mt < 2; mt++)
        #pragma unroll
        for (int half = 0; half < 2; half++) {
            int row = rowBase + warpM * 32 + mt * 16 + (lane >> 2) + half * 8;
            if (row < M) {
                #pragma unroll
                for (int nt = 0; nt < NT; nt++) {
                    int col = wcb + nt * 8 + (lane & 3) * 2;
                    uint32_t u = pack_bf16x2(c[mt][nt][half * 2], c[mt][nt][half * 2 + 1]);
                    *reinterpret_cast<uint32_t*>(C + (size_t)row * Nc + col) = u;
                }
            }
        }

    float* sP = reinterpret_cast<float*>(&sA[0][0]);   // [128][4]
    __syncthreads();
    float asc[NT * 2], adc[NT * 2];
    #pragma unroll
    for (int nt = 0; nt < NT; nt++)
        #pragma unroll
        for (int j = 0; j < 2; j++) {
            int col = wcb + nt * 8 + (lane & 3) * 2 + j;
            asc[nt * 2 + j] = a_src[col];
            adc[nt * 2 + j] = a_dst[col];
        }
    #pragma unroll
    for (int mt = 0; mt < 2; mt++)
        #pragma unroll
        for (int half = 0; half < 2; half++) {
            float ss = 0.f, sd = 0.f;
            #pragma unroll
            for (int nt = 0; nt < NT; nt++)
                #pragma unroll
                for (int j = 0; j < 2; j++) {
                    float v = c[mt][nt][half * 2 + j];
                    ss += v * asc[nt * 2 + j];
                    sd += v * adc[nt * 2 + j];
                }
            #pragma unroll
            for (int o = 1; o <= 2; o <<= 1) {
                ss += __shfl_xor_sync(0xffffffffu, ss, o);
                sd += __shfl_xor_sync(0xffffffffu, sd, o);
            }
            if ((lane & 3) == 0) {
                int rl = warpM * 32 + mt * 16 + (lane >> 2) + half * 8;
                sP[rl * 4 + warpN * 2 + 0] = ss;
                sP[rl * 4 + warpN * 2 + 1] = sd;
            }
        }
    __syncthreads();
    if (tid < 128) {
        int row = rowBase + tid;
        if (row < M) {
            g_as[row] = sP[tid * 4 + 0] + sP[tid * 4 + 2];
            g_ad[row] = sP[tid * 4 + 1] + sP[tid * 4 + 3];
        }
    }
}

// ---------------- layer-1 aggregation (warp per dst, depth-2 prefetch) ---------
__global__ void __launch_bounds__(256) agg1_kernel(const float* __restrict__ b1) {
    int dst = (blockIdx.x * blockDim.x + threadIdx.x) >> 5;
    int lane = threadIdx.x & 31;
    if (dst >= GN) return;
    const int head = lane >> 2;

    const float ad = g_ad1[(size_t)dst * GH + head];
    const int rs = g_rowptr[dst];
    const int re = g_rowptr[dst + 1];

    // depth-2 prefetch
    uint4 u0 = make_uint4(0, 0, 0, 0), u1 = make_uint4(0, 0, 0, 0);
    float a0v = 0.f, a1v = 0.f;
    if (rs < re) {
        int s0 = g_srcs[rs];
        u0 = *reinterpret_cast<const uint4*>(g_h1b + (size_t)s0 * GF1 + lane * 8);
        a0v = g_as1[(size_t)s0 * GH + head];
    }
    if (rs + 1 < re) {
        int s1 = g_srcs[rs + 1];
        u1 = *reinterpret_cast<const uint4*>(g_h1b + (size_t)s1 * GF1 + lane * 8);
        a1v = g_as1[(size_t)s1 * GH + head];
    }

    float acc[8];
    float den;
    {   // self loop
        float w = __expf(lrelu(g_as1[(size_t)dst * GH + head] + ad));
        den = w;
        uint4 us = *reinterpret_cast<const uint4*>(g_h1b + (size_t)dst * GF1 + lane * 8);
        float2 f0 = unpack_bf16x2(us.x), f1 = unpack_bf16x2(us.y);
        float2 f2 = unpack_bf16x2(us.z), f3 = unpack_bf16x2(us.w);
        acc[0] = w * f0.x; acc[1] = w * f0.y; acc[2] = w * f1.x; acc[3] = w * f1.y;
        acc[4] = w * f2.x; acc[5] = w * f2.y; acc[6] = w * f3.x; acc[7] = w * f3.y;
    }
    for (int e = rs; e < re; e++) {
        uint4 uc = u0;
        float ac = a0v;
        u0 = u1; a0v = a1v;
        if (e + 2 < re) {
            int s2 = g_srcs[e + 2];
            u1 = *reinterpret_cast<const uint4*>(g_h1b + (size_t)s2 * GF1 + lane * 8);
            a1v = g_as1[(size_t)s2 * GH + head];
        }
        float w = __expf(lrelu(ac + ad));
        den += w;
        float2 f0 = unpack_bf16x2(uc.x), f1 = unpack_bf16x2(uc.y);
        float2 f2 = unpack_bf16x2(uc.z), f3 = unpack_bf16x2(uc.w);
        acc[0] += w * f0.x; acc[1] += w * f0.y; acc[2] += w * f1.x; acc[3] += w * f1.y;
        acc[4] += w * f2.x; acc[5] += w * f2.y; acc[6] += w * f3.x; acc[7] += w * f3.y;
    }
    float inv = 1.f / den;
    float4 bb0 = *reinterpret_cast<const float4*>(b1 + lane * 8);
    float4 bb1 = *reinterpret_cast<const float4*>(b1 + lane * 8 + 4);
    float bv[8] = {bb0.x, bb0.y, bb0.z, bb0.w, bb1.x, bb1.y, bb1.z, bb1.w};
    uint4 st;
    uint32_t* stp = reinterpret_cast<uint32_t*>(&st);
    #pragma unroll
    for (int p = 0; p < 4; p++) {
        float v0 = fmaxf(acc[2 * p] * inv + bv[2 * p], 0.f);
        float v1 = fmaxf(acc[2 * p + 1] * inv + bv[2 * p + 1], 0.f);
        stp[p] = pack_bf16x2(v0, v1);
    }
    *reinterpret_cast<uint4*>(g_out1b + (size_t)dst * GF1 + lane * 8) = st;
}

// ---------------- layer-2 aggregation + bias + log_softmax ---------------------
__global__ void __launch_bounds__(256) agg2_kernel(const float* __restrict__ b2,
                                                   float* __restrict__ out) {
    int dst = (blockIdx.x * blockDim.x + threadIdx.x) >> 5;
    int lane = threadIdx.x & 31;
    if (dst >= GN) return;

    const float ad = g_ad2[dst];
    const int rs = g_rowptr[dst];
    const int re = g_rowptr[dst + 1];

    // depth-2 prefetch
    uint32_t u0 = 0, u1 = 0;
    float a0v = 0.f, a1v = 0.f;
    if (rs < re) {
        int s0 = g_srcs[rs];
        u0 = *reinterpret_cast<const uint32_t*>(g_h2b + (size_t)s0 * GOUT + 2 * lane);
        a0v = g_as2[s0];
    }
    if (rs + 1 < re) {
        int s1 = g_srcs[rs + 1];
        u1 = *reinterpret_cast<const uint32_t*>(g_h2b + (size_t)s1 * GOUT + 2 * lane);
        a1v = g_as2[s1];
    }

    float den, a0, a1;
    {
        float w = __expf(lrelu(g_as2[dst] + ad));
        den = w;
        uint32_t us = *reinterpret_cast<const uint32_t*>(g_h2b + (size_t)dst * GOUT + 2 * lane);
        float2 f = unpack_bf16x2(us);
        a0 = w * f.x;
        a1 = w * f.y;
    }
    for (int e = rs; e < re; e++) {
        uint32_t uc = u0;
        float ac = a0v;
        u0 = u1; a0v = a1v;
        if (e + 2 < re) {
            int s2 = g_srcs[e + 2];
            u1 = *reinterpret_cast<const uint32_t*>(g_h2b + (size_t)s2 * GOUT + 2 * lane);
            a1v = g_as2[s2];
        }
        float w = __expf(lrelu(ac + ad));
        den += w;
        float2 f = unpack_bf16x2(uc);
        a0 += w * f.x;
        a1 += w * f.y;
    }
    float2 bb = *reinterpret_cast<const float2*>(b2 + 2 * lane);
    float inv = 1.f / den;
    float v0 = a0 * inv + bb.x;
    float v1 = a1 * inv + bb.y;

    float m = fmaxf(v0, v1);
    #pragma unroll
    for (int o = 16; o; o >>= 1) m = fmaxf(m, __shfl_xor_sync(0xffffffffu, m, o));
    float s = __expf(v0 - m) + __expf(v1 - m);
    #pragma unroll
    for (int o = 16; o; o >>= 1) s += __shfl_xor_sync(0xffffffffu, s, o);
    float ls = __logf(s) + m;

    float2 st = make_float2(v0 - ls, v1 - ls);
    *reinterpret_cast<float2*>(out + (size_t)dst * GOUT + 2 * lane) = st;
}

// ---------------- launch --------------------------------------------------------
extern "C" void kernel_launch(void* const* d_in, const int* in_sizes, int n_in,
                              void* d_out, int out_size) {
    const float* x      = (const float*)d_in[0];
    const int*   ei     = (const int*)d_in[1];
    const float* W1     = (const float*)d_in[2];
    const float* a_src1 = (const float*)d_in[3];
    const float* a_dst1 = (const float*)d_in[4];
    const float* b1     = (const float*)d_in[5];
    const float* W2     = (const float*)d_in[6];
    const float* a_src2 = (const float*)d_in[7];
    const float* a_dst2 = (const float*)d_in[8];
    const float* b2     = (const float*)d_in[9];
    float* out = (float*)d_out;
    const int E = in_sizes[1] / 2;

    __nv_bfloat16 *w1p, *w2p, *h1p, *out1p, *h2p;
    float *as1p, *ad1p, *as2p, *ad2p;
    void* cntp;
    cudaGetSymbolAddress((void**)&w1p, g_w1b);
    cudaGetSymbolAddress((void**)&w2p, g_w2b);
    cudaGetSymbolAddress((void**)&h1p, g_h1b);
    cudaGetSymbolAddress((void**)&out1p, g_out1b);
    cudaGetSymbolAddress((void**)&h2p, g_h2b);
    cudaGetSymbolAddress((void**)&as1p, g_as1);
    cudaGetSymbolAddress((void**)&ad1p, g_ad1);
    cudaGetSymbolAddress((void**)&as2p, g_as2);
    cudaGetSymbolAddress((void**)&ad2p, g_ad2);
    cudaGetSymbolAddress(&cntp, g_cnt);

    // host-side resources, created once
    static cudaStream_t s_side = nullptr;
    static cudaEvent_t s_fork = nullptr, s_join = nullptr;
    if (s_side == nullptr) {
        cudaStreamCreateWithFlags(&s_side, cudaStreamNonBlocking);
        cudaEventCreateWithFlags(&s_fork, cudaEventDisableTiming);
        cudaEventCreateWithFlags(&s_join, cudaEventDisableTiming);
    }

    // fork: CSR chain on side stream, GEMM1 chain on main stream
    cudaEventRecord(s_fork, 0);
    cudaStreamWaitEvent(s_side, s_fork, 0);

    // --- side: CSR build
    cudaMemsetAsync(cntp, 0, GN * sizeof(int), s_side);
    hist_kernel<<<(E / 4 + 4 + 255) / 256, 256, 0, s_side>>>(ei, E);
    block_sum_kernel<<<NB, 256, 0, s_side>>>();
    scan_apply_kernel<<<NB, 256, 0, s_side>>>();
    scatter_kernel<<<(E / 4 + 4 + 255) / 256, 256, 0, s_side>>>(ei, E);
    cudaEventRecord(s_join, s_side);

    // --- main: W conversion + GEMM1 (+ fused alpha1)
    convw_kernel<<<132, 256>>>(W1, W2);
    gemm1_kernel<<<(GN + 63) / 64, 256>>>(x, w1p, h1p, a_src1, a_dst1, as1p, ad1p);

    // join
    cudaStreamWaitEvent(0, s_join, 0);

    agg1_kernel<<<(GN + 7) / 8, 256>>>(b1);
    gemm2_kernel<<<dim3(1, (GN + 127) / 128), 256>>>(
        out1p, w2p, h2p, GN, GF1, GOUT, a_src2, a_dst2, as2p, ad2p);
    agg2_kernel<<<(GN + 7) / 8, 256>>>(b2, out);
}

// round 12
// speedup vs baseline: 1.2459x; 1.0266x over previous
#include <cuda_runtime.h>
#include <cuda_bf16.h>
#include <cstdint>

#define GN 50000      // nodes
#define GE 800000     // edges (without self loops)
#define GIN 256       // in_dim
#define GH 8          // heads layer1
#define GHID 32       // hidden per head
#define GF1 256       // H*HID
#define GOUT 64       // classes
#define NB  ((GN + 255) / 256)

// ---------------- scratch (device globals) -------------------------------------
__device__ __nv_bfloat16 g_w1b[GIN * GF1];           // W1 bf16
__device__ __nv_bfloat16 g_w2b[GF1 * GOUT];          // W2 bf16
__device__ __nv_bfloat16 g_h1b[(size_t)GN * GF1];    // x @ W1, bf16
__device__ __nv_bfloat16 g_out1b[(size_t)GN * GF1];  // relu(gat1), bf16
__device__ __nv_bfloat16 g_h2b[(size_t)GN * GOUT];   // gat1_out @ W2, bf16
__device__ float g_as1[(size_t)GN * GH];
__device__ float g_ad1[(size_t)GN * GH];
__device__ float g_as2[GN];
__device__ float g_ad2[GN];
__device__ int   g_cnt[GN];        // histogram (zero at graph entry; re-zeroed at tail)
__device__ int   g_cur[GN];        // scatter cursor
__device__ int   g_rowptr[GN + 1];
__device__ int   g_srcs[GE];       // src ids bucketed by dst

__device__ __forceinline__ float lrelu(float x) { return fmaxf(x, 0.2f * x); }

__device__ __forceinline__ uint32_t pack_bf16x2(float lo, float hi) {
    uint32_t r;
    asm("cvt.rn.bf16x2.f32 %0, %1, %2;" : "=r"(r) : "f"(hi), "f"(lo));
    return r;
}
__device__ __forceinline__ float2 unpack_bf16x2(uint32_t u) {
    float2 f;
    f.x = __uint_as_float(u << 16);
    f.y = __uint_as_float(u & 0xffff0000u);
    return f;
}
__device__ __forceinline__ uint32_t smem_u32(const void* p) {
    return (uint32_t)__cvta_generic_to_shared(p);
}
__device__ __forceinline__ void cp_async16(uint32_t dst, const void* src, bool pred) {
    int sz = pred ? 16 : 0;
    asm volatile("cp.async.cg.shared.global [%0], [%1], 16, %2;\n"
                 :: "r"(dst), "l"(src), "r"(sz));
}
__device__ __forceinline__ void cp_commit() {
    asm volatile("cp.async.commit_group;\n");
}
__device__ __forceinline__ void ldsm_x4(uint32_t* r, uint32_t addr) {
    asm volatile("ldmatrix.sync.aligned.m8n8.x4.shared.b16 {%0,%1,%2,%3}, [%4];\n"
                 : "=r"(r[0]), "=r"(r[1]), "=r"(r[2]), "=r"(r[3]) : "r"(addr));
}
__device__ __forceinline__ void ldsm_x4_t(uint32_t* r, uint32_t addr) {
    asm volatile("ldmatrix.sync.aligned.m8n8.x4.trans.shared.b16 {%0,%1,%2,%3}, [%4];\n"
                 : "=r"(r[0]), "=r"(r[1]), "=r"(r[2]), "=r"(r[3]) : "r"(addr));
}
__device__ __forceinline__ void mma_bf16(float* c, const uint32_t* a, uint32_t b0, uint32_t b1) {
    asm volatile(
        "mma.sync.aligned.m16n8k16.row.col.f32.bf16.bf16.f32 "
        "{%0,%1,%2,%3},{%4,%5,%6,%7},{%8,%9},{%0,%1,%2,%3};\n"
        : "+f"(c[0]), "+f"(c[1]), "+f"(c[2]), "+f"(c[3])
        : "r"(a[0]), "r"(a[1]), "r"(a[2]), "r"(a[3]), "r"(b0), "r"(b1));
}

// ---------------- CSR build (side stream) --------------------------------------
__global__ void hist_kernel(const int* __restrict__ ei, int E) {
    int i = blockIdx.x * blockDim.x + threadIdx.x;
    int n4 = E >> 2;
    if (i < n4) {
        int4 d = reinterpret_cast<const int4*>(ei + E)[i];
        atomicAdd(&g_cnt[d.x], 1);
        atomicAdd(&g_cnt[d.y], 1);
        atomicAdd(&g_cnt[d.z], 1);
        atomicAdd(&g_cnt[d.w], 1);
    } else if (i < n4 + (E & 3)) {
        atomicAdd(&g_cnt[ei[E + n4 * 4 + (i - n4)]], 1);
    }
}

// single-pass scan: each block sums its prefix from g_cnt (read-only),
// writes rowptr and cursors into g_cur (g_cnt untouched -> no race).
__global__ void scan_apply_kernel() {
    __shared__ int ws[8];
    __shared__ int s_off;
    int tid = threadIdx.x, lane = tid & 31, wid = tid >> 5;

    // block offset = sum of g_cnt[0 .. blockIdx.x*256)
    int limit = blockIdx.x * 256;
    int a = 0;
    for (int j = tid; j < limit; j += 256) a += g_cnt[j];
    #pragma unroll
    for (int o = 16; o; o >>= 1) a += __shfl_xor_sync(0xffffffffu, a, o);
    if (lane == 0) ws[wid] = a;
    __syncthreads();
    if (tid == 0) {
        int t = 0;
        #pragma unroll
        for (int k = 0; k < 8; k++) t += ws[k];
        s_off = t;
    }
    __syncthreads();

    int i = blockIdx.x * 256 + tid;
    int v = (i < GN) ? g_cnt[i] : 0;
    int s = v;
    #pragma unroll
    for (int o = 1; o < 32; o <<= 1) {
        int t = __shfl_up_sync(0xffffffffu, s, o);
        if (lane >= o) s += t;
    }
    if (lane == 31) ws[wid] = s;
    __syncthreads();
    if (wid == 0 && lane < 8) {
        int t = ws[lane];
        #pragma unroll
        for (int o = 1; o < 8; o <<= 1) {
            int u = __shfl_up_sync(0xffu, t, o);
            if (lane >= o) t += u;
        }
        ws[lane] = t;
    }
    __syncthreads();
    int incl = s + (wid ? ws[wid - 1] : 0) + s_off;
    if (i < GN) {
        g_rowptr[i + 1] = incl;
        g_cur[i] = incl - v;   // exclusive prefix -> scatter cursor
    }
    if (i == 0) g_rowptr[0] = 0;
}

__global__ void scatter_kernel(const int* __restrict__ ei, int E) {
    int i = blockIdx.x * blockDim.x + threadIdx.x;
    int n4 = E >> 2;
    if (i < n4) {
        int4 sv = reinterpret_cast<const int4*>(ei)[i];
        int4 dv = reinterpret_cast<const int4*>(ei + E)[i];
        g_srcs[atomicAdd(&g_cur[dv.x], 1)] = sv.x;
        g_srcs[atomicAdd(&g_cur[dv.y], 1)] = sv.y;
        g_srcs[atomicAdd(&g_cur[dv.z], 1)] = sv.z;
        g_srcs[atomicAdd(&g_cur[dv.w], 1)] = sv.w;
    } else if (i < n4 + (E & 3)) {
        int e = n4 * 4 + (i - n4);
        g_srcs[atomicAdd(&g_cur[ei[E + e]], 1)] = ei[e];
    }
}

// re-zero g_cnt for the next graph replay (off critical path, side stream tail)
__global__ void zero_cnt_kernel() {
    int i = blockIdx.x * blockDim.x + threadIdx.x;
    if (i < GN) g_cnt[i] = 0;
}

// ---------------- W1/W2 fp32 -> bf16 (main stream, before gemm1) ---------------
__global__ void convw_kernel(const float* __restrict__ W1, const float* __restrict__ W2) {
    int i = blockIdx.x * blockDim.x + threadIdx.x;
    int stride = gridDim.x * blockDim.x;
    const int T1 = GIN * GF1 / 8;
    for (int t = i; t < T1; t += stride) {
        float4 v0 = reinterpret_cast<const float4*>(W1)[t * 2];
        float4 v1 = reinterpret_cast<const float4*>(W1)[t * 2 + 1];
        uint4 u = make_uint4(pack_bf16x2(v0.x, v0.y), pack_bf16x2(v0.z, v0.w),
                             pack_bf16x2(v1.x, v1.y), pack_bf16x2(v1.z, v1.w));
        reinterpret_cast<uint4*>(g_w1b)[t] = u;
    }
    const int T2 = GF1 * GOUT / 8;
    for (int t = i; t < T2; t += stride) {
        float4 v0 = reinterpret_cast<const float4*>(W2)[t * 2];
        float4 v1 = reinterpret_cast<const float4*>(W2)[t * 2 + 1];
        uint4 u = make_uint4(pack_bf16x2(v0.x, v0.y), pack_bf16x2(v0.z, v0.w),
                             pack_bf16x2(v1.x, v1.y), pack_bf16x2(v1.z, v1.w));
        reinterpret_cast<uint4*>(g_w2b)[t] = u;
    }
}

// ---------------- GEMM1: A fp32 (x), B bf16 (W1), BM=64 BN=256 -----------------
__global__ void __launch_bounds__(256) gemm1_kernel(
    const float* __restrict__ A, const __nv_bfloat16* __restrict__ B,
    __nv_bfloat16* __restrict__ C,
    const float* __restrict__ a_src, const float* __restrict__ a_dst,
    float* __restrict__ g_as, float* __restrict__ g_ad) {
    constexpr int BN = 256, SBS = BN + 8;
    constexpr int A_ELEM = 64 * 40;
    constexpr int B_ELEM = 32 * SBS;
    __shared__ __align__(16) __nv_bfloat16 sA[2][A_ELEM];
    __shared__ __align__(16) __nv_bfloat16 sB[2][B_ELEM];

    const int tid = threadIdx.x, lane = tid & 31, wid = tid >> 5;
    const int warpM = wid & 1, warpN = wid >> 1;      // 2 x 4
    const int rowBase = blockIdx.x * 64;
    const int wcb = warpN * 64;

    const uint32_t sAu = smem_u32(&sA[0][0]), sBu = smem_u32(&sB[0][0]);
    const int aRow = warpM * 32 + (lane & 7) + ((lane >> 3) & 1) * 8;
    const uint32_t aAddr = sAu + (uint32_t)(aRow * 40 + ((lane >> 4) * 8)) * 2;
    const int bRow = (lane & 7) + ((lane >> 3) & 1) * 8;
    const uint32_t bAddr = sBu + (uint32_t)(bRow * SBS + wcb + (lane >> 4) * 8) * 2;

    const int ar0 = tid >> 3, ac0 = (tid & 7) * 4;
    const int ar1 = (tid + 256) >> 3, ac1 = ac0;

    auto ldA = [&](float4* r, int k0) {
        int row0 = rowBase + ar0, row1 = rowBase + ar1;
        r[0] = (row0 < GN) ? *reinterpret_cast<const float4*>(A + (size_t)row0 * GIN + k0 + ac0)
                           : make_float4(0.f, 0.f, 0.f, 0.f);
        r[1] = (row1 < GN) ? *reinterpret_cast<const float4*>(A + (size_t)row1 * GIN + k0 + ac1)
                           : make_float4(0.f, 0.f, 0.f, 0.f);
    };
    auto stA = [&](int buf, const float4* r) {
        uint2 p0 = make_uint2(pack_bf16x2(r[0].x, r[0].y), pack_bf16x2(r[0].z, r[0].w));
        uint2 p1 = make_uint2(pack_bf16x2(r[1].x, r[1].y), pack_bf16x2(r[1].z, r[1].w));
        *reinterpret_cast<uint2*>(&sA[buf][ar0 * 40 + ac0]) = p0;
        *reinterpret_cast<uint2*>(&sA[buf][ar1 * 40 + ac1]) = p1;
    };
    auto stageB = [&](int buf, int k0) {
        #pragma unroll
        for (int i2 = 0; i2 < 4; i2++) {
            int f = tid + i2 * 256;
            int krow = f >> 5, c8 = (f & 31) * 8;
            uint32_t dst = sBu + (uint32_t)(buf * B_ELEM + krow * SBS + c8) * 2;
            cp_async16(dst, B + (size_t)(k0 + krow) * BN + c8, true);
        }
    };

    float c[2][8][4];
    #pragma unroll
    for (int i = 0; i < 2; i++)
        #pragma unroll
        for (int j = 0; j < 8; j++)
            #pragma unroll
            for (int q = 0; q < 4; q++) c[i][j][q] = 0.f;

    constexpr int S = GIN / 32;
    float4 ra[2];
    ldA(ra, 0);
    stA(0, ra);
    stageB(0, 0);
    cp_commit();

    float4 rn[2];
    for (int s = 0; s < S; s++) {
        const int buf = s & 1;
        if (s + 1 < S) {
            ldA(rn, (s + 1) * 32);
            stageB(buf ^ 1, (s + 1) * 32);
            cp_commit();
            asm volatile("cp.async.wait_group 1;\n");
        } else {
            asm volatile("cp.async.wait_group 0;\n");
        }
        __syncthreads();
        const uint32_t aB = aAddr + buf * A_ELEM * 2;
        const uint32_t bB = bAddr + buf * B_ELEM * 2;
        #pragma unroll
        for (int ks = 0; ks < 2; ks++) {
            uint32_t a[2][4];
            #pragma unroll
            for (int mt = 0; mt < 2; mt++)
                ldsm_x4(a[mt], aB + (uint32_t)(mt * 16 * 40 + ks * 16) * 2);
            uint32_t b[4][4];
            #pragma unroll
            for (int np = 0; np < 4; np++)
                ldsm_x4_t(b[np], bB + (uint32_t)(ks * 16 * SBS + np * 16) * 2);
            #pragma unroll
            for (int mt = 0; mt < 2; mt++)
                #pragma unroll
                for (int nt = 0; nt < 8; nt++) {
                    int np = nt >> 1;
                    mma_bf16(c[mt][nt], a[mt], b[np][(nt & 1) * 2], b[np][(nt & 1) * 2 + 1]);
                }
        }
        if (s + 1 < S) stA(buf ^ 1, rn);
        __syncthreads();
    }

    #pragma unroll
    for (int mt = 0; mt < 2; mt++)
        #pragma unroll
        for (int half = 0; half < 2; half++) {
            int row = rowBase + warpM * 32 + mt * 16 + (lane >> 2) + half * 8;
            if (row < GN) {
                #pragma unroll
                for (int nt = 0; nt < 8; nt++) {
                    int col = wcb + nt * 8 + (lane & 3) * 2;
                    uint32_t u = pack_bf16x2(c[mt][nt][half * 2], c[mt][nt][half * 2 + 1]);
                    *reinterpret_cast<uint32_t*>(C + (size_t)row * GF1 + col) = u;
                }
            }
        }

    float asc[16], adc[16];
    #pragma unroll
    for (int nt = 0; nt < 8; nt++)
        #pragma unroll
        for (int j = 0; j < 2; j++) {
            int col = wcb + nt * 8 + (lane & 3) * 2 + j;
            asc[nt * 2 + j] = a_src[col];
            adc[nt * 2 + j] = a_dst[col];
        }
    int headBase = wcb >> 5;
    #pragma unroll
    for (int mt = 0; mt < 2; mt++)
        #pragma unroll
        for (int half = 0; half < 2; half++) {
            int row = rowBase + warpM * 32 + mt * 16 + (lane >> 2) + half * 8;
            float ss0 = 0.f, ss1 = 0.f, sd0 = 0.f, sd1 = 0.f;
            #pragma unroll
            for (int nt = 0; nt < 8; nt++)
                #pragma unroll
                for (int j = 0; j < 2; j++) {
                    float v = c[mt][nt][half * 2 + j];
                    if (nt < 4) { ss0 += v * asc[nt * 2 + j]; sd0 += v * adc[nt * 2 + j]; }
                    else        { ss1 += v * asc[nt * 2 + j]; sd1 += v * adc[nt * 2 + j]; }
                }
            #pragma unroll
            for (int o = 1; o <= 2; o <<= 1) {
                ss0 += __shfl_xor_sync(0xffffffffu, ss0, o);
                ss1 += __shfl_xor_sync(0xffffffffu, ss1, o);
                sd0 += __shfl_xor_sync(0xffffffffu, sd0, o);
                sd1 += __shfl_xor_sync(0xffffffffu, sd1, o);
            }
            if ((lane & 3) == 0 && row < GN) {
                g_as[(size_t)row * GH + headBase]     = ss0;
                g_as[(size_t)row * GH + headBase + 1] = ss1;
                g_ad[(size_t)row * GH + headBase]     = sd0;
                g_ad[(size_t)row * GH + headBase + 1] = sd1;
            }
        }
}

// ---------------- GEMM2: bf16 A (out1), BN=64, fused alpha2 --------------------
__global__ void __launch_bounds__(256) gemm2_kernel(
    const __nv_bfloat16* __restrict__ A, const __nv_bfloat16* __restrict__ B,
    __nv_bfloat16* __restrict__ C, int M, int K, int Nc,
    const float* __restrict__ a_src, const float* __restrict__ a_dst,
    float* __restrict__ g_as, float* __restrict__ g_ad) {
    constexpr int BN = 64, NT = 4, NP = 2, SBS = BN + 8;
    constexpr int A_ELEM = 128 * 40;
    constexpr int B_ELEM = 32 * SBS;
    __shared__ __align__(16) __nv_bfloat16 sA[2][A_ELEM];
    __shared__ __align__(16) __nv_bfloat16 sB[2][B_ELEM];

    const int tid = threadIdx.x, lane = tid & 31, wid = tid >> 5;
    const int warpM = wid & 3, warpN = wid >> 2;
    const int rowBase = blockIdx.y * 128;
    const int wcb = warpN * (BN / 2);

    const uint32_t sAu = smem_u32(&sA[0][0]), sBu = smem_u32(&sB[0][0]);
    const int aRow = warpM * 32 + (lane & 7) + ((lane >> 3) & 1) * 8;
    const uint32_t aAddr = sAu + (uint32_t)(aRow * 40 + ((lane >> 4) * 8)) * 2;
    const int bRow = (lane & 7) + ((lane >> 3) & 1) * 8;
    const uint32_t bAddr = sBu + (uint32_t)(bRow * SBS + wcb + (lane >> 4) * 8) * 2;

    auto stageA = [&](int buf, int k0) {
        #pragma unroll
        for (int i2 = 0; i2 < 2; i2++) {
            int f = tid + i2 * 256;
            int r = f >> 2, c8 = (f & 3) * 8;
            int row = rowBase + r;
            uint32_t dst = sAu + (uint32_t)(buf * A_ELEM + r * 40 + c8) * 2;
            cp_async16(dst, A + (size_t)row * K + k0 + c8, row < M);
        }
    };
    auto stageB = [&](int buf, int k0) {
        int krow = tid >> 3, c8 = (tid & 7) * 8;
        uint32_t dst = sBu + (uint32_t)(buf * B_ELEM + krow * SBS + c8) * 2;
        cp_async16(dst, B + (size_t)(k0 + krow) * Nc + c8, true);
    };

    float c[2][NT][4];
    #pragma unroll
    for (int i = 0; i < 2; i++)
        #pragma unroll
        for (int j = 0; j < NT; j++)
            #pragma unroll
            for (int q = 0; q < 4; q++) c[i][j][q] = 0.f;

    const int S = K / 32;
    stageA(0, 0);
    stageB(0, 0);
    cp_commit();

    for (int s = 0; s < S; s++) {
        const int buf = s & 1;
        if (s + 1 < S) {
            stageA(buf ^ 1, (s + 1) * 32);
            stageB(buf ^ 1, (s + 1) * 32);
            cp_commit();
            asm volatile("cp.async.wait_group 1;\n");
        } else {
            asm volatile("cp.async.wait_group 0;\n");
        }
        __syncthreads();
        const uint32_t aB = aAddr + buf * A_ELEM * 2;
        const uint32_t bB = bAddr + buf * B_ELEM * 2;
        #pragma unroll
        for (int ks = 0; ks < 2; ks++) {
            uint32_t a[2][4];
            #pragma unroll
            for (int mt = 0; mt < 2; mt++)
                ldsm_x4(a[mt], aB + (uint32_t)(mt * 16 * 40 + ks * 16) * 2);
            uint32_t b[NP][4];
            #pragma unroll
            for (int np = 0; np < NP; np++)
                ldsm_x4_t(b[np], bB + (uint32_t)(ks * 16 * SBS + np * 16) * 2);
            #pragma unroll
            for (int mt = 0; mt < 2; mt++)
                #pragma unroll
                for (int nt = 0; nt < NT; nt++) {
                    int np = nt >> 1;
                    mma_bf16(c[mt][nt], a[mt], b[np][(nt & 1) * 2], b[np][(nt & 1) * 2 + 1]);
                }
        }
        __syncthreads();
    }

    #pragma unroll
    for (int mt = 0; mt < 2; mt++)
        #pragma unroll
        for (int half = 0; half < 2; half++) {
            int row = rowBase + warpM * 32 + mt * 16 + (lane >> 2) + half * 8;
            if (row < M) {
                #pragma unroll
                for (int nt = 0; nt < NT; nt++) {
                    int col = wcb + nt * 8 + (lane & 3) * 2;
                    uint32_t u = pack_bf16x2(c[mt][nt][half * 2], c[mt][nt][half * 2 + 1]);
                    *reinterpret_cast<uint32_t*>(C + (size_t)row * Nc + col) = u;
                }
            }
        }

    float* sP = reinterpret_cast<float*>(&sA[0][0]);   // [128][4]
    __syncthreads();
    float asc[NT * 2], adc[NT * 2];
    #pragma unroll
    for (int nt = 0; nt < NT; nt++)
        #pragma unroll
        for (int j = 0; j < 2; j++) {
            int col = wcb + nt * 8 + (lane & 3) * 2 + j;
            asc[nt * 2 + j] = a_src[col];
            adc[nt * 2 + j] = a_dst[col];
        }
    #pragma unroll
    for (int mt = 0; mt < 2; mt++)
        #pragma unroll
        for (int half = 0; half < 2; half++) {
            float ss = 0.f, sd = 0.f;
            #pragma unroll
            for (int nt = 0; nt < NT; nt++)
                #pragma unroll
                for (int j = 0; j < 2; j++) {
                    float v = c[mt][nt][half * 2 + j];
                    ss += v * asc[nt * 2 + j];
                    sd += v * adc[nt * 2 + j];
                }
            #pragma unroll
            for (int o = 1; o <= 2; o <<= 1) {
                ss += __shfl_xor_sync(0xffffffffu, ss, o);
                sd += __shfl_xor_sync(0xffffffffu, sd, o);
            }
            if ((lane & 3) == 0) {
                int rl = warpM * 32 + mt * 16 + (lane >> 2) + half * 8;
                sP[rl * 4 + warpN * 2 + 0] = ss;
                sP[rl * 4 + warpN * 2 + 1] = sd;
            }
        }
    __syncthreads();
    if (tid < 128) {
        int row = rowBase + tid;
        if (row < M) {
            g_as[row] = sP[tid * 4 + 0] + sP[tid * 4 + 2];
            g_ad[row] = sP[tid * 4 + 1] + sP[tid * 4 + 3];
        }
    }
}

// ---------------- layer-1 aggregation (warp per dst, depth-1 prefetch) ---------
__global__ void __launch_bounds__(256) agg1_kernel(const float* __restrict__ b1) {
    int dst = (blockIdx.x * blockDim.x + threadIdx.x) >> 5;
    int lane = threadIdx.x & 31;
    if (dst >= GN) return;
    const int head = lane >> 2;

    const float ad = g_ad1[(size_t)dst * GH + head];
    const int rs = g_rowptr[dst];
    const int re = g_rowptr[dst + 1];

    int src0 = (rs < re) ? g_srcs[rs] : 0;
    uint4 u = *reinterpret_cast<const uint4*>(g_h1b + (size_t)src0 * GF1 + lane * 8);
    float av = g_as1[(size_t)src0 * GH + head];

    float acc[8];
    float den;
    {   // self loop
        float w = __expf(lrelu(g_as1[(size_t)dst * GH + head] + ad));
        den = w;
        uint4 us = *reinterpret_cast<const uint4*>(g_h1b + (size_t)dst * GF1 + lane * 8);
        float2 f0 = unpack_bf16x2(us.x), f1 = unpack_bf16x2(us.y);
        float2 f2 = unpack_bf16x2(us.z), f3 = unpack_bf16x2(us.w);
        acc[0] = w * f0.x; acc[1] = w * f0.y; acc[2] = w * f1.x; acc[3] = w * f1.y;
        acc[4] = w * f2.x; acc[5] = w * f2.y; acc[6] = w * f3.x; acc[7] = w * f3.y;
    }
    for (int e = rs; e < re; e++) {
        uint4 uc = u;
        float ac = av;
        if (e + 1 < re) {
            int s2 = g_srcs[e + 1];
            u = *reinterpret_cast<const uint4*>(g_h1b + (size_t)s2 * GF1 + lane * 8);
            av = g_as1[(size_t)s2 * GH + head];
        }
        float w = __expf(lrelu(ac + ad));
        den += w;
        float2 f0 = unpack_bf16x2(uc.x), f1 = unpack_bf16x2(uc.y);
        float2 f2 = unpack_bf16x2(uc.z), f3 = unpack_bf16x2(uc.w);
        acc[0] += w * f0.x; acc[1] += w * f0.y; acc[2] += w * f1.x; acc[3] += w * f1.y;
        acc[4] += w * f2.x; acc[5] += w * f2.y; acc[6] += w * f3.x; acc[7] += w * f3.y;
    }
    float inv = 1.f / den;
    float4 bb0 = *reinterpret_cast<const float4*>(b1 + lane * 8);
    float4 bb1 = *reinterpret_cast<const float4*>(b1 + lane * 8 + 4);
    float bv[8] = {bb0.x, bb0.y, bb0.z, bb0.w, bb1.x, bb1.y, bb1.z, bb1.w};
    uint4 st;
    uint32_t* stp = reinterpret_cast<uint32_t*>(&st);
    #pragma unroll
    for (int p = 0; p < 4; p++) {
        float v0 = fmaxf(acc[2 * p] * inv + bv[2 * p], 0.f);
        float v1 = fmaxf(acc[2 * p + 1] * inv + bv[2 * p + 1], 0.f);
        stp[p] = pack_bf16x2(v0, v1);
    }
    *reinterpret_cast<uint4*>(g_out1b + (size_t)dst * GF1 + lane * 8) = st;
}

// ---------------- layer-2 aggregation + bias + log_softmax ---------------------
__global__ void __launch_bounds__(256) agg2_kernel(const float* __restrict__ b2,
                                                   float* __restrict__ out) {
    int dst = (blockIdx.x * blockDim.x + threadIdx.x) >> 5;
    int lane = threadIdx.x & 31;
    if (dst >= GN) return;

    const float ad = g_ad2[dst];
    const int rs = g_rowptr[dst];
    const int re = g_rowptr[dst + 1];

    int src0 = (rs < re) ? g_srcs[rs] : 0;
    uint32_t u = *reinterpret_cast<const uint32_t*>(g_h2b + (size_t)src0 * GOUT + 2 * lane);
    float av = g_as2[src0];

    float den, a0, a1;
    {
        float w = __expf(lrelu(g_as2[dst] + ad));
        den = w;
        uint32_t us = *reinterpret_cast<const uint32_t*>(g_h2b + (size_t)dst * GOUT + 2 * lane);
        float2 f = unpack_bf16x2(us);
        a0 = w * f.x;
        a1 = w * f.y;
    }
    for (int e = rs; e < re; e++) {
        uint32_t uc = u;
        float ac = av;
        if (e + 1 < re) {
            int s2 = g_srcs[e + 1];
            u = *reinterpret_cast<const uint32_t*>(g_h2b + (size_t)s2 * GOUT + 2 * lane);
            av = g_as2[s2];
        }
        float w = __expf(lrelu(ac + ad));
        den += w;
        float2 f = unpack_bf16x2(uc);
        a0 += w * f.x;
        a1 += w * f.y;
    }
    float2 bb = *reinterpret_cast<const float2*>(b2 + 2 * lane);
    float inv = 1.f / den;
    float v0 = a0 * inv + bb.x;
    float v1 = a1 * inv + bb.y;

    float m = fmaxf(v0, v1);
    #pragma unroll
    for (int o = 16; o; o >>= 1) m = fmaxf(m, __shfl_xor_sync(0xffffffffu, m, o));
    float s = __expf(v0 - m) + __expf(v1 - m);
    #pragma unroll
    for (int o = 16; o; o >>= 1) s += __shfl_xor_sync(0xffffffffu, s, o);
    float ls = __logf(s) + m;

    float2 st = make_float2(v0 - ls, v1 - ls);
    *reinterpret_cast<float2*>(out + (size_t)dst * GOUT + 2 * lane) = st;
}

// ---------------- launch --------------------------------------------------------
extern "C" void kernel_launch(void* const* d_in, const int* in_sizes, int n_in,
                              void* d_out, int out_size) {
    const float* x      = (const float*)d_in[0];
    const int*   ei     = (const int*)d_in[1];
    const float* W1     = (const float*)d_in[2];
    const float* a_src1 = (const float*)d_in[3];
    const float* a_dst1 = (const float*)d_in[4];
    const float* b1     = (const float*)d_in[5];
    const float* W2     = (const float*)d_in[6];
    const float* a_src2 = (const float*)d_in[7];
    const float* a_dst2 = (const float*)d_in[8];
    const float* b2     = (const float*)d_in[9];
    float* out = (float*)d_out;
    const int E = in_sizes[1] / 2;

    __nv_bfloat16 *w1p, *w2p, *h1p, *out1p, *h2p;
    float *as1p, *ad1p, *as2p, *ad2p;
    cudaGetSymbolAddress((void**)&w1p, g_w1b);
    cudaGetSymbolAddress((void**)&w2p, g_w2b);
    cudaGetSymbolAddress((void**)&h1p, g_h1b);
    cudaGetSymbolAddress((void**)&out1p, g_out1b);
    cudaGetSymbolAddress((void**)&h2p, g_h2b);
    cudaGetSymbolAddress((void**)&as1p, g_as1);
    cudaGetSymbolAddress((void**)&ad1p, g_ad1);
    cudaGetSymbolAddress((void**)&as2p, g_as2);
    cudaGetSymbolAddress((void**)&ad2p, g_ad2);

    // host-side resources, created once
    static cudaStream_t s_side = nullptr;
    static cudaEvent_t s_fork = nullptr, s_join = nullptr, s_join2 = nullptr;
    if (s_side == nullptr) {
        cudaStreamCreateWithFlags(&s_side, cudaStreamNonBlocking);
        cudaEventCreateWithFlags(&s_fork, cudaEventDisableTiming);
        cudaEventCreateWithFlags(&s_join, cudaEventDisableTiming);
        cudaEventCreateWithFlags(&s_join2, cudaEventDisableTiming);
    }

    // fork: CSR chain on side stream, GEMM1 chain on main stream
    cudaEventRecord(s_fork, 0);
    cudaStreamWaitEvent(s_side, s_fork, 0);

    // --- side: CSR build (g_cnt is zero at graph entry; re-zeroed at tail)
    hist_kernel<<<(E / 4 + 4 + 255) / 256, 256, 0, s_side>>>(ei, E);
    scan_apply_kernel<<<NB, 256, 0, s_side>>>();
    scatter_kernel<<<(E / 4 + 4 + 255) / 256, 256, 0, s_side>>>(ei, E);
    cudaEventRecord(s_join, s_side);
    zero_cnt_kernel<<<NB, 256, 0, s_side>>>();   // off critical path
    cudaEventRecord(s_join2, s_side);            // join ALL side work at graph exit

    // --- main: W conversion + GEMM1 (+ fused alpha1)
    convw_kernel<<<132, 256>>>(W1, W2);
    gemm1_kernel<<<(GN + 63) / 64, 256>>>(x, w1p, h1p, a_src1, a_dst1, as1p, ad1p);

    // join CSR outputs before aggregation
    cudaStreamWaitEvent(0, s_join, 0);

    agg1_kernel<<<(GN + 7) / 8, 256>>>(b1);
    gemm2_kernel<<<dim3(1, (GN + 127) / 128), 256>>>(
        out1p, w2p, h2p, GN, GF1, GOUT, a_src2, a_dst2, as2p, ad2p);
    agg2_kernel<<<(GN + 7) / 8, 256>>>(b2, out);

    // join the side-stream tail (zero_cnt) so capture ends fully joined
    cudaStreamWaitEvent(0, s_join2, 0);
}

// round 13
// speedup vs baseline: 1.2619x; 1.0128x over previous
#include <cuda_runtime.h>
#include <cuda_bf16.h>
#include <cstdint>

#define GN 50000      // nodes
#define GE 800000     // edges (without self loops)
#define GIN 256       // in_dim
#define GH 8          // heads layer1
#define GHID 32       // hidden per head
#define GF1 256       // H*HID
#define GOUT 64       // classes
#define NB  ((GN + 255) / 256)

// ---------------- scratch (device globals) -------------------------------------
__device__ __nv_bfloat16 g_w1b[GIN * GF1];           // W1 bf16
__device__ __nv_bfloat16 g_w2b[GF1 * GOUT];          // W2 bf16
__device__ __nv_bfloat16 g_h1b[(size_t)GN * GF1];    // x @ W1, bf16
__device__ __nv_bfloat16 g_out1b[(size_t)GN * GF1];  // relu(gat1), bf16
__device__ __nv_bfloat16 g_h2b[(size_t)GN * GOUT];   // gat1_out @ W2, bf16
__device__ float g_as1[(size_t)GN * GH];
__device__ float g_ad1[(size_t)GN * GH];
__device__ float g_as2[GN];
__device__ float g_ad2[GN];
__device__ int   g_cnt[GN];        // histogram -> cursor
__device__ int   g_rowptr[GN + 1];
__device__ int   g_srcs[GE];       // src ids bucketed by dst
__device__ int   g_bsum[NB + 1];

__device__ __forceinline__ float lrelu(float x) { return fmaxf(x, 0.2f * x); }

__device__ __forceinline__ uint32_t pack_bf16x2(float lo, float hi) {
    uint32_t r;
    asm("cvt.rn.bf16x2.f32 %0, %1, %2;" : "=r"(r) : "f"(hi), "f"(lo));
    return r;
}
__device__ __forceinline__ float2 unpack_bf16x2(uint32_t u) {
    float2 f;
    f.x = __uint_as_float(u << 16);
    f.y = __uint_as_float(u & 0xffff0000u);
    return f;
}
__device__ __forceinline__ uint32_t smem_u32(const void* p) {
    return (uint32_t)__cvta_generic_to_shared(p);
}
__device__ __forceinline__ void cp_async16(uint32_t dst, const void* src, bool pred) {
    int sz = pred ? 16 : 0;
    asm volatile("cp.async.cg.shared.global [%0], [%1], 16, %2;\n"
                 :: "r"(dst), "l"(src), "r"(sz));
}
__device__ __forceinline__ void cp_commit() {
    asm volatile("cp.async.commit_group;\n");
}
__device__ __forceinline__ void ldsm_x4(uint32_t* r, uint32_t addr) {
    asm volatile("ldmatrix.sync.aligned.m8n8.x4.shared.b16 {%0,%1,%2,%3}, [%4];\n"
                 : "=r"(r[0]), "=r"(r[1]), "=r"(r[2]), "=r"(r[3]) : "r"(addr));
}
__device__ __forceinline__ void ldsm_x4_t(uint32_t* r, uint32_t addr) {
    asm volatile("ldmatrix.sync.aligned.m8n8.x4.trans.shared.b16 {%0,%1,%2,%3}, [%4];\n"
                 : "=r"(r[0]), "=r"(r[1]), "=r"(r[2]), "=r"(r[3]) : "r"(addr));
}
__device__ __forceinline__ void mma_bf16(float* c, const uint32_t* a, uint32_t b0, uint32_t b1) {
    asm volatile(
        "mma.sync.aligned.m16n8k16.row.col.f32.bf16.bf16.f32 "
        "{%0,%1,%2,%3},{%4,%5,%6,%7},{%8,%9},{%0,%1,%2,%3};\n"
        : "+f"(c[0]), "+f"(c[1]), "+f"(c[2]), "+f"(c[3])
        : "r"(a[0]), "r"(a[1]), "r"(a[2]), "r"(a[3]), "r"(b0), "r"(b1));
}

// ---------------- CSR build (side stream) --------------------------------------
__global__ void hist_kernel(const int* __restrict__ ei, int E) {
    int i = blockIdx.x * blockDim.x + threadIdx.x;
    int n4 = E >> 2;
    if (i < n4) {
        int4 d = reinterpret_cast<const int4*>(ei + E)[i];
        atomicAdd(&g_cnt[d.x], 1);
        atomicAdd(&g_cnt[d.y], 1);
        atomicAdd(&g_cnt[d.z], 1);
        atomicAdd(&g_cnt[d.w], 1);
    } else if (i < n4 + (E & 3)) {
        atomicAdd(&g_cnt[ei[E + n4 * 4 + (i - n4)]], 1);
    }
}

__global__ void block_sum_kernel() {
    __shared__ int ws[8];
    int i = blockIdx.x * 256 + threadIdx.x;
    int v = (i < GN) ? g_cnt[i] : 0;
    int s = v;
    #pragma unroll
    for (int o = 16; o; o >>= 1) s += __shfl_xor_sync(0xffffffffu, s, o);
    if ((threadIdx.x & 31) == 0) ws[threadIdx.x >> 5] = s;
    __syncthreads();
    if (threadIdx.x < 8) {
        int t = ws[threadIdx.x];
        #pragma unroll
        for (int o = 4; o; o >>= 1) t += __shfl_xor_sync(0xffu, t, o);
        if (threadIdx.x == 0) g_bsum[blockIdx.x] = t;
    }
}

__global__ void scan_apply_kernel() {
    __shared__ int ws[8];
    __shared__ int s_off;
    int tid = threadIdx.x, lane = tid & 31, wid = tid >> 5;

    int a = 0;
    for (int j = tid; j < blockIdx.x; j += 256) a += g_bsum[j];
    #pragma unroll
    for (int o = 16; o; o >>= 1) a += __shfl_xor_sync(0xffffffffu, a, o);
    if (lane == 0) ws[wid] = a;
    __syncthreads();
    if (tid == 0) {
        int t = 0;
        #pragma unroll
        for (int k = 0; k < 8; k++) t += ws[k];
        s_off = t;
    }
    __syncthreads();

    int i = blockIdx.x * 256 + tid;
    int v = (i < GN) ? g_cnt[i] : 0;
    int s = v;
    #pragma unroll
    for (int o = 1; o < 32; o <<= 1) {
        int t = __shfl_up_sync(0xffffffffu, s, o);
        if (lane >= o) s += t;
    }
    if (lane == 31) ws[wid] = s;
    __syncthreads();
    if (wid == 0 && lane < 8) {
        int t = ws[lane];
        #pragma unroll
        for (int o = 1; o < 8; o <<= 1) {
            int u = __shfl_up_sync(0xffu, t, o);
            if (lane >= o) t += u;
        }
        ws[lane] = t;
    }
    __syncthreads();
    int incl = s + (wid ? ws[wid - 1] : 0) + s_off;
    if (i < GN) {
        g_rowptr[i + 1] = incl;
        g_cnt[i] = incl - v;   // exclusive -> scatter cursor
    }
    if (i == 0) g_rowptr[0] = 0;
}

__global__ void scatter_kernel(const int* __restrict__ ei, int E) {
    int i = blockIdx.x * blockDim.x + threadIdx.x;
    int n4 = E >> 2;
    if (i < n4) {
        int4 sv = reinterpret_cast<const int4*>(ei)[i];
        int4 dv = reinterpret_cast<const int4*>(ei + E)[i];
        g_srcs[atomicAdd(&g_cnt[dv.x], 1)] = sv.x;
        g_srcs[atomicAdd(&g_cnt[dv.y], 1)] = sv.y;
        g_srcs[atomicAdd(&g_cnt[dv.z], 1)] = sv.z;
        g_srcs[atomicAdd(&g_cnt[dv.w], 1)] = sv.w;
    } else if (i < n4 + (E & 3)) {
        int e = n4 * 4 + (i - n4);
        g_srcs[atomicAdd(&g_cnt[ei[E + e]], 1)] = ei[e];
    }
}

// ---------------- W1/W2 fp32 -> bf16 (main stream, before gemm1) ---------------
__global__ void convw_kernel(const float* __restrict__ W1, const float* __restrict__ W2) {
    int i = blockIdx.x * blockDim.x + threadIdx.x;
    int stride = gridDim.x * blockDim.x;
    const int T1 = GIN * GF1 / 8;
    for (int t = i; t < T1; t += stride) {
        float4 v0 = reinterpret_cast<const float4*>(W1)[t * 2];
        float4 v1 = reinterpret_cast<const float4*>(W1)[t * 2 + 1];
        uint4 u = make_uint4(pack_bf16x2(v0.x, v0.y), pack_bf16x2(v0.z, v0.w),
                             pack_bf16x2(v1.x, v1.y), pack_bf16x2(v1.z, v1.w));
        reinterpret_cast<uint4*>(g_w1b)[t] = u;
    }
    const int T2 = GF1 * GOUT / 8;
    for (int t = i; t < T2; t += stride) {
        float4 v0 = reinterpret_cast<const float4*>(W2)[t * 2];
        float4 v1 = reinterpret_cast<const float4*>(W2)[t * 2 + 1];
        uint4 u = make_uint4(pack_bf16x2(v0.x, v0.y), pack_bf16x2(v0.z, v0.w),
                             pack_bf16x2(v1.x, v1.y), pack_bf16x2(v1.z, v1.w));
        reinterpret_cast<uint4*>(g_w2b)[t] = u;
    }
}

// ---------------- GEMM1: A fp32 (x), B bf16 (W1), BM=64 BN=256 -----------------
__global__ void __launch_bounds__(256) gemm1_kernel(
    const float* __restrict__ A, const __nv_bfloat16* __restrict__ B,
    __nv_bfloat16* __restrict__ C,
    const float* __restrict__ a_src, const float* __restrict__ a_dst,
    float* __restrict__ g_as, float* __restrict__ g_ad) {
    constexpr int BN = 256, SBS = BN + 8;
    constexpr int A_ELEM = 64 * 40;
    constexpr int B_ELEM = 32 * SBS;
    __shared__ __align__(16) __nv_bfloat16 sA[2][A_ELEM];
    __shared__ __align__(16) __nv_bfloat16 sB[2][B_ELEM];

    const int tid = threadIdx.x, lane = tid & 31, wid = tid >> 5;
    const int warpM = wid & 1, warpN = wid >> 1;      // 2 x 4
    const int rowBase = blockIdx.x * 64;
    const int wcb = warpN * 64;

    const uint32_t sAu = smem_u32(&sA[0][0]), sBu = smem_u32(&sB[0][0]);
    const int aRow = warpM * 32 + (lane & 7) + ((lane >> 3) & 1) * 8;
    const uint32_t aAddr = sAu + (uint32_t)(aRow * 40 + ((lane >> 4) * 8)) * 2;
    const int bRow = (lane & 7) + ((lane >> 3) & 1) * 8;
    const uint32_t bAddr = sBu + (uint32_t)(bRow * SBS + wcb + (lane >> 4) * 8) * 2;

    const int ar0 = tid >> 3, ac0 = (tid & 7) * 4;
    const int ar1 = (tid + 256) >> 3, ac1 = ac0;

    auto ldA = [&](float4* r, int k0) {
        int row0 = rowBase + ar0, row1 = rowBase + ar1;
        r[0] = (row0 < GN) ? *reinterpret_cast<const float4*>(A + (size_t)row0 * GIN + k0 + ac0)
                           : make_float4(0.f, 0.f, 0.f, 0.f);
        r[1] = (row1 < GN) ? *reinterpret_cast<const float4*>(A + (size_t)row1 * GIN + k0 + ac1)
                           : make_float4(0.f, 0.f, 0.f, 0.f);
    };
    auto stA = [&](int buf, const float4* r) {
        uint2 p0 = make_uint2(pack_bf16x2(r[0].x, r[0].y), pack_bf16x2(r[0].z, r[0].w));
        uint2 p1 = make_uint2(pack_bf16x2(r[1].x, r[1].y), pack_bf16x2(r[1].z, r[1].w));
        *reinterpret_cast<uint2*>(&sA[buf][ar0 * 40 + ac0]) = p0;
        *reinterpret_cast<uint2*>(&sA[buf][ar1 * 40 + ac1]) = p1;
    };
    auto stageB = [&](int buf, int k0) {
        #pragma unroll
        for (int i2 = 0; i2 < 4; i2++) {
            int f = tid + i2 * 256;
            int krow = f >> 5, c8 = (f & 31) * 8;
            uint32_t dst = sBu + (uint32_t)(buf * B_ELEM + krow * SBS + c8) * 2;
            cp_async16(dst, B + (size_t)(k0 + krow) * BN + c8, true);
        }
    };

    float c[2][8][4];
    #pragma unroll
    for (int i = 0; i < 2; i++)
        #pragma unroll
        for (int j = 0; j < 8; j++)
            #pragma unroll
            for (int q = 0; q < 4; q++) c[i][j][q] = 0.f;

    constexpr int S = GIN / 32;
    float4 ra[2];
    ldA(ra, 0);
    stA(0, ra);
    stageB(0, 0);
    cp_commit();

    float4 rn[2];
    for (int s = 0; s < S; s++) {
        const int buf = s & 1;
        if (s + 1 < S) {
            ldA(rn, (s + 1) * 32);
            stageB(buf ^ 1, (s + 1) * 32);
            cp_commit();
            asm volatile("cp.async.wait_group 1;\n");
        } else {
            asm volatile("cp.async.wait_group 0;\n");
        }
        __syncthreads();
        const uint32_t aB = aAddr + buf * A_ELEM * 2;
        const uint32_t bB = bAddr + buf * B_ELEM * 2;
        #pragma unroll
        for (int ks = 0; ks < 2; ks++) {
            uint32_t a[2][4];
            #pragma unroll
            for (int mt = 0; mt < 2; mt++)
                ldsm_x4(a[mt], aB + (uint32_t)(mt * 16 * 40 + ks * 16) * 2);
            uint32_t b[4][4];
            #pragma unroll
            for (int np = 0; np < 4; np++)
                ldsm_x4_t(b[np], bB + (uint32_t)(ks * 16 * SBS + np * 16) * 2);
            #pragma unroll
            for (int mt = 0; mt < 2; mt++)
                #pragma unroll
                for (int nt = 0; nt < 8; nt++) {
                    int np = nt >> 1;
                    mma_bf16(c[mt][nt], a[mt], b[np][(nt & 1) * 2], b[np][(nt & 1) * 2 + 1]);
                }
        }
        if (s + 1 < S) stA(buf ^ 1, rn);
        __syncthreads();
    }

    #pragma unroll
    for (int mt = 0; mt < 2; mt++)
        #pragma unroll
        for (int half = 0; half < 2; half++) {
            int row = rowBase + warpM * 32 + mt * 16 + (lane >> 2) + half * 8;
            if (row < GN) {
                #pragma unroll
                for (int nt = 0; nt < 8; nt++) {
                    int col = wcb + nt * 8 + (lane & 3) * 2;
                    uint32_t u = pack_bf16x2(c[mt][nt][half * 2], c[mt][nt][half * 2 + 1]);
                    *reinterpret_cast<uint32_t*>(C + (size_t)row * GF1 + col) = u;
                }
            }
        }

    float asc[16], adc[16];
    #pragma unroll
    for (int nt = 0; nt < 8; nt++)
        #pragma unroll
        for (int j = 0; j < 2; j++) {
            int col = wcb + nt * 8 + (lane & 3) * 2 + j;
            asc[nt * 2 + j] = a_src[col];
            adc[nt * 2 + j] = a_dst[col];
        }
    int headBase = wcb >> 5;
    #pragma unroll
    for (int mt = 0; mt < 2; mt++)
        #pragma unroll
        for (int half = 0; half < 2; half++) {
            int row = rowBase + warpM * 32 + mt * 16 + (lane >> 2) + half * 8;
            float ss0 = 0.f, ss1 = 0.f, sd0 = 0.f, sd1 = 0.f;
            #pragma unroll
            for (int nt = 0; nt < 8; nt++)
                #pragma unroll
                for (int j = 0; j < 2; j++) {
                    float v = c[mt][nt][half * 2 + j];
                    if (nt < 4) { ss0 += v * asc[nt * 2 + j]; sd0 += v * adc[nt * 2 + j]; }
                    else        { ss1 += v * asc[nt * 2 + j]; sd1 += v * adc[nt * 2 + j]; }
                }
            #pragma unroll
            for (int o = 1; o <= 2; o <<= 1) {
                ss0 += __shfl_xor_sync(0xffffffffu, ss0, o);
                ss1 += __shfl_xor_sync(0xffffffffu, ss1, o);
                sd0 += __shfl_xor_sync(0xffffffffu, sd0, o);
                sd1 += __shfl_xor_sync(0xffffffffu, sd1, o);
            }
            if ((lane & 3) == 0 && row < GN) {
                g_as[(size_t)row * GH + headBase]     = ss0;
                g_as[(size_t)row * GH + headBase + 1] = ss1;
                g_ad[(size_t)row * GH + headBase]     = sd0;
                g_ad[(size_t)row * GH + headBase + 1] = sd1;
            }
        }
}

// ---------------- GEMM2: bf16 A (out1), BN=64, fused alpha2 --------------------
__global__ void __launch_bounds__(256) gemm2_kernel(
    const __nv_bfloat16* __restrict__ A, const __nv_bfloat16* __restrict__ B,
    __nv_bfloat16* __restrict__ C, int M, int K, int Nc,
    const float* __restrict__ a_src, const float* __restrict__ a_dst,
    float* __restrict__ g_as, float* __restrict__ g_ad) {
    constexpr int BN = 64, NT = 4, NP = 2, SBS = BN + 8;
    constexpr int A_ELEM = 128 * 40;
    constexpr int B_ELEM = 32 * SBS;
    __shared__ __align__(16) __nv_bfloat16 sA[2][A_ELEM];
    __shared__ __align__(16) __nv_bfloat16 sB[2][B_ELEM];

    const int tid = threadIdx.x, lane = tid & 31, wid = tid >> 5;
    const int warpM = wid & 3, warpN = wid >> 2;
    const int rowBase = blockIdx.y * 128;
    const int wcb = warpN * (BN / 2);

    const uint32_t sAu = smem_u32(&sA[0][0]), sBu = smem_u32(&sB[0][0]);
    const int aRow = warpM * 32 + (lane & 7) + ((lane >> 3) & 1) * 8;
    const uint32_t aAddr = sAu + (uint32_t)(aRow * 40 + ((lane >> 4) * 8)) * 2;
    const int bRow = (lane & 7) + ((lane >> 3) & 1) * 8;
    const uint32_t bAddr = sBu + (uint32_t)(bRow * SBS + wcb + (lane >> 4) * 8) * 2;

    auto stageA = [&](int buf, int k0) {
        #pragma unroll
        for (int i2 = 0; i2 < 2; i2++) {
            int f = tid + i2 * 256;
            int r = f >> 2, c8 = (f & 3) * 8;
            int row = rowBase + r;
            uint32_t dst = sAu + (uint32_t)(buf * A_ELEM + r * 40 + c8) * 2;
            cp_async16(dst, A + (size_t)row * K + k0 + c8, row < M);
        }
    };
    auto stageB = [&](int buf, int k0) {
        int krow = tid >> 3, c8 = (tid & 7) * 8;
        uint32_t dst = sBu + (uint32_t)(buf * B_ELEM + krow * SBS + c8) * 2;
        cp_async16(dst, B + (size_t)(k0 + krow) * Nc + c8, true);
    };

    float c[2][NT][4];
    #pragma unroll
    for (int i = 0; i < 2; i++)
        #pragma unroll
        for (int j = 0; j < NT; j++)
            #pragma unroll
            for (int q = 0; q < 4; q++) c[i][j][q] = 0.f;

    const int S = K / 32;
    stageA(0, 0);
    stageB(0, 0);
    cp_commit();

    for (int s = 0; s < S; s++) {
        const int buf = s & 1;
        if (s + 1 < S) {
            stageA(buf ^ 1, (s + 1) * 32);
            stageB(buf ^ 1, (s + 1) * 32);
            cp_commit();
            asm volatile("cp.async.wait_group 1;\n");
        } else {
            asm volatile("cp.async.wait_group 0;\n");
        }
        __syncthreads();
        const uint32_t aB = aAddr + buf * A_ELEM * 2;
        const uint32_t bB = bAddr + buf * B_ELEM * 2;
        #pragma unroll
        for (int ks = 0; ks < 2; ks++) {
            uint32_t a[2][4];
            #pragma unroll
            for (int mt = 0; mt < 2; mt++)
                ldsm_x4(a[mt], aB + (uint32_t)(mt * 16 * 40 + ks * 16) * 2);
            uint32_t b[NP][4];
            #pragma unroll
            for (int np = 0; np < NP; np++)
                ldsm_x4_t(b[np], bB + (uint32_t)(ks * 16 * SBS + np * 16) * 2);
            #pragma unroll
            for (int mt = 0; mt < 2; mt++)
                #pragma unroll
                for (int nt = 0; nt < NT; nt++) {
                    int np = nt >> 1;
                    mma_bf16(c[mt][nt], a[mt], b[np][(nt & 1) * 2], b[np][(nt & 1) * 2 + 1]);
                }
        }
        __syncthreads();
    }

    #pragma unroll
    for (int mt = 0; mt < 2; mt++)
        #pragma unroll
        for (int half = 0; half < 2; half++) {
            int row = rowBase + warpM * 32 + mt * 16 + (lane >> 2) + half * 8;
            if (row < M) {
                #pragma unroll
                for (int nt = 0; nt < NT; nt++) {
                    int col = wcb + nt * 8 + (lane & 3) * 2;
                    uint32_t u = pack_bf16x2(c[mt][nt][half * 2], c[mt][nt][half * 2 + 1]);
                    *reinterpret_cast<uint32_t*>(C + (size_t)row * Nc + col) = u;
                }
            }
        }

    float* sP = reinterpret_cast<float*>(&sA[0][0]);   // [128][4]
    __syncthreads();
    float asc[NT * 2], adc[NT * 2];
    #pragma unroll
    for (int nt = 0; nt < NT; nt++)
        #pragma unroll
        for (int j = 0; j < 2; j++) {
            int col = wcb + nt * 8 + (lane & 3) * 2 + j;
            asc[nt * 2 + j] = a_src[col];
            adc[nt * 2 + j] = a_dst[col];
        }
    #pragma unroll
    for (int mt = 0; mt < 2; mt++)
        #pragma unroll
        for (int half = 0; half < 2; half++) {
            float ss = 0.f, sd = 0.f;
            #pragma unroll
            for (int nt = 0; nt < NT; nt++)
                #pragma unroll
                for (int j = 0; j < 2; j++) {
                    float v = c[mt][nt][half * 2 + j];
                    ss += v * asc[nt * 2 + j];
                    sd += v * adc[nt * 2 + j];
                }
            #pragma unroll
            for (int o = 1; o <= 2; o <<= 1) {
                ss += __shfl_xor_sync(0xffffffffu, ss, o);
                sd += __shfl_xor_sync(0xffffffffu, sd, o);
            }
            if ((lane & 3) == 0) {
                int rl = warpM * 32 + mt * 16 + (lane >> 2) + half * 8;
                sP[rl * 4 + warpN * 2 + 0] = ss;
                sP[rl * 4 + warpN * 2 + 1] = sd;
            }
        }
    __syncthreads();
    if (tid < 128) {
        int row = rowBase + tid;
        if (row < M) {
            g_as[row] = sP[tid * 4 + 0] + sP[tid * 4 + 2];
            g_ad[row] = sP[tid * 4 + 1] + sP[tid * 4 + 3];
        }
    }
}

// ---------------- layer-1 aggregation (warp per dst, 64-thread blocks) ---------
__global__ void __launch_bounds__(64) agg1_kernel(const float* __restrict__ b1) {
    int dst = (blockIdx.x * blockDim.x + threadIdx.x) >> 5;
    int lane = threadIdx.x & 31;
    if (dst >= GN) return;
    const int head = lane >> 2;

    const float ad = g_ad1[(size_t)dst * GH + head];
    const int rs = g_rowptr[dst];
    const int re = g_rowptr[dst + 1];

    int src0 = (rs < re) ? g_srcs[rs] : 0;
    uint4 u = *reinterpret_cast<const uint4*>(g_h1b + (size_t)src0 * GF1 + lane * 8);
    float av = g_as1[(size_t)src0 * GH + head];

    float acc[8];
    float den;
    {   // self loop
        float w = __expf(lrelu(g_as1[(size_t)dst * GH + head] + ad));
        den = w;
        uint4 us = *reinterpret_cast<const uint4*>(g_h1b + (size_t)dst * GF1 + lane * 8);
        float2 f0 = unpack_bf16x2(us.x), f1 = unpack_bf16x2(us.y);
        float2 f2 = unpack_bf16x2(us.z), f3 = unpack_bf16x2(us.w);
        acc[0] = w * f0.x; acc[1] = w * f0.y; acc[2] = w * f1.x; acc[3] = w * f1.y;
        acc[4] = w * f2.x; acc[5] = w * f2.y; acc[6] = w * f3.x; acc[7] = w * f3.y;
    }
    for (int e = rs; e < re; e++) {
        uint4 uc = u;
        float ac = av;
        if (e + 1 < re) {
            int s2 = g_srcs[e + 1];
            u = *reinterpret_cast<const uint4*>(g_h1b + (size_t)s2 * GF1 + lane * 8);
            av = g_as1[(size_t)s2 * GH + head];
        }
        float w = __expf(lrelu(ac + ad));
        den += w;
        float2 f0 = unpack_bf16x2(uc.x), f1 = unpack_bf16x2(uc.y);
        float2 f2 = unpack_bf16x2(uc.z), f3 = unpack_bf16x2(uc.w);
        acc[0] += w * f0.x; acc[1] += w * f0.y; acc[2] += w * f1.x; acc[3] += w * f1.y;
        acc[4] += w * f2.x; acc[5] += w * f2.y; acc[6] += w * f3.x; acc[7] += w * f3.y;
    }
    float inv = 1.f / den;
    float4 bb0 = *reinterpret_cast<const float4*>(b1 + lane * 8);
    float4 bb1 = *reinterpret_cast<const float4*>(b1 + lane * 8 + 4);
    float bv[8] = {bb0.x, bb0.y, bb0.z, bb0.w, bb1.x, bb1.y, bb1.z, bb1.w};
    uint4 st;
    uint32_t* stp = reinterpret_cast<uint32_t*>(&st);
    #pragma unroll
    for (int p = 0; p < 4; p++) {
        float v0 = fmaxf(acc[2 * p] * inv + bv[2 * p], 0.f);
        float v1 = fmaxf(acc[2 * p + 1] * inv + bv[2 * p + 1], 0.f);
        stp[p] = pack_bf16x2(v0, v1);
    }
    *reinterpret_cast<uint4*>(g_out1b + (size_t)dst * GF1 + lane * 8) = st;
}

// ---------------- layer-2 aggregation + bias + log_softmax (64-thr blocks) -----
__global__ void __launch_bounds__(64) agg2_kernel(const float* __restrict__ b2,
                                                  float* __restrict__ out) {
    int dst = (blockIdx.x * blockDim.x + threadIdx.x) >> 5;
    int lane = threadIdx.x & 31;
    if (dst >= GN) return;

    const float ad = g_ad2[dst];
    const int rs = g_rowptr[dst];
    const int re = g_rowptr[dst + 1];

    int src0 = (rs < re) ? g_srcs[rs] : 0;
    uint32_t u = *reinterpret_cast<const uint32_t*>(g_h2b + (size_t)src0 * GOUT + 2 * lane);
    float av = g_as2[src0];

    float den, a0, a1;
    {
        float w = __expf(lrelu(g_as2[dst] + ad));
        den = w;
        uint32_t us = *reinterpret_cast<const uint32_t*>(g_h2b + (size_t)dst * GOUT + 2 * lane);
        float2 f = unpack_bf16x2(us);
        a0 = w * f.x;
        a1 = w * f.y;
    }
    for (int e = rs; e < re; e++) {
        uint32_t uc = u;
        float ac = av;
        if (e + 1 < re) {
            int s2 = g_srcs[e + 1];
            u = *reinterpret_cast<const uint32_t*>(g_h2b + (size_t)s2 * GOUT + 2 * lane);
            av = g_as2[s2];
        }
        float w = __expf(lrelu(ac + ad));
        den += w;
        float2 f = unpack_bf16x2(uc);
        a0 += w * f.x;
        a1 += w * f.y;
    }
    float2 bb = *reinterpret_cast<const float2*>(b2 + 2 * lane);
    float inv = 1.f / den;
    float v0 = a0 * inv + bb.x;
    float v1 = a1 * inv + bb.y;

    float m = fmaxf(v0, v1);
    #pragma unroll
    for (int o = 16; o; o >>= 1) m = fmaxf(m, __shfl_xor_sync(0xffffffffu, m, o));
    float s = __expf(v0 - m) + __expf(v1 - m);
    #pragma unroll
    for (int o = 16; o; o >>= 1) s += __shfl_xor_sync(0xffffffffu, s, o);
    float ls = __logf(s) + m;

    float2 st = make_float2(v0 - ls, v1 - ls);
    *reinterpret_cast<float2*>(out + (size_t)dst * GOUT + 2 * lane) = st;
}

// ---------------- launch --------------------------------------------------------
extern "C" void kernel_launch(void* const* d_in, const int* in_sizes, int n_in,
                              void* d_out, int out_size) {
    const float* x      = (const float*)d_in[0];
    const int*   ei     = (const int*)d_in[1];
    const float* W1     = (const float*)d_in[2];
    const float* a_src1 = (const float*)d_in[3];
    const float* a_dst1 = (const float*)d_in[4];
    const float* b1     = (const float*)d_in[5];
    const float* W2     = (const float*)d_in[6];
    const float* a_src2 = (const float*)d_in[7];
    const float* a_dst2 = (const float*)d_in[8];
    const float* b2     = (const float*)d_in[9];
    float* out = (float*)d_out;
    const int E = in_sizes[1] / 2;

    __nv_bfloat16 *w1p, *w2p, *h1p, *out1p, *h2p;
    float *as1p, *ad1p, *as2p, *ad2p;
    void* cntp;
    cudaGetSymbolAddress((void**)&w1p, g_w1b);
    cudaGetSymbolAddress((void**)&w2p, g_w2b);
    cudaGetSymbolAddress((void**)&h1p, g_h1b);
    cudaGetSymbolAddress((void**)&out1p, g_out1b);
    cudaGetSymbolAddress((void**)&h2p, g_h2b);
    cudaGetSymbolAddress((void**)&as1p, g_as1);
    cudaGetSymbolAddress((void**)&ad1p, g_ad1);
    cudaGetSymbolAddress((void**)&as2p, g_as2);
    cudaGetSymbolAddress((void**)&ad2p, g_ad2);
    cudaGetSymbolAddress(&cntp, g_cnt);

    // host-side resources, created once
    static cudaStream_t s_side = nullptr;
    static cudaEvent_t s_fork = nullptr, s_join = nullptr;
    if (s_side == nullptr) {
        cudaStreamCreateWithFlags(&s_side, cudaStreamNonBlocking);
        cudaEventCreateWithFlags(&s_fork, cudaEventDisableTiming);
        cudaEventCreateWithFlags(&s_join, cudaEventDisableTiming);
    }

    // fork: CSR chain on side stream, GEMM1 chain on main stream
    cudaEventRecord(s_fork, 0);
    cudaStreamWaitEvent(s_side, s_fork, 0);

    // --- side: CSR build
    cudaMemsetAsync(cntp, 0, GN * sizeof(int), s_side);
    hist_kernel<<<(E / 4 + 4 + 255) / 256, 256, 0, s_side>>>(ei, E);
    block_sum_kernel<<<NB, 256, 0, s_side>>>();
    scan_apply_kernel<<<NB, 256, 0, s_side>>>();
    scatter_kernel<<<(E / 4 + 4 + 255) / 256, 256, 0, s_side>>>(ei, E);
    cudaEventRecord(s_join, s_side);

    // --- main: W conversion + GEMM1 (+ fused alpha1)
    convw_kernel<<<132, 256>>>(W1, W2);
    gemm1_kernel<<<(GN + 63) / 64, 256>>>(x, w1p, h1p, a_src1, a_dst1, as1p, ad1p);

    // join
    cudaStreamWaitEvent(0, s_join, 0);

    agg1_kernel<<<(GN + 1) / 2, 64>>>(b1);
    gemm2_kernel<<<dim3(1, (GN + 127) / 128), 256>>>(
        out1p, w2p, h2p, GN, GF1, GOUT, a_src2, a_dst2, as2p, ad2p);
    agg2_kernel<<<(GN + 1) / 2, 64>>>(b2, out);
}